// round 10
// baseline (speedup 1.0000x reference)
#include <cuda_runtime.h>
#include <cuda_fp16.h>
#include <math.h>
#include <stdint.h>

#define SQ   2048
#define DM   2048
#define DH   128
#define NH   16
#define DL   512
#define BB   4
#define MTOT (BB*SQ)

// ---------------- scratch ------------------------------------------------------
__device__ __half g_xhi[(size_t)MTOT * DM],  g_xlo[(size_t)MTOT * DM];
__device__ __half g_lathi[(size_t)MTOT * DL], g_latlo[(size_t)MTOT * DL];
__device__ __half g_khi[(size_t)MTOT * DM],  g_klo[(size_t)MTOT * DM];
__device__ __half g_qhi[(size_t)MTOT * DM],  g_qlo[(size_t)MTOT * DM];
__device__ __half g_ctxhi[(size_t)MTOT * DM], g_ctxlo[(size_t)MTOT * DM];
__device__ __half g_vthi[(size_t)BB * NH * DH * SQ], g_vtlo[(size_t)BB * NH * DH * SQ];
__device__ __half g_wdh[(size_t)DM * DL], g_wdl[(size_t)DM * DL];
__device__ __half g_wukh[(size_t)DL * DM], g_wukl[(size_t)DL * DM];
__device__ __half g_wuvh[(size_t)DL * DM], g_wuvl[(size_t)DL * DM];
__device__ __half g_wqh[(size_t)DM * DM],  g_wql[(size_t)DM * DM];
__device__ __half g_woh[(size_t)DM * DM],  g_wol[(size_t)DM * DM];
__device__ float  g_S[(size_t)BB * NH * SQ * SQ];     // 1.07 GB
__device__ __half g_P[(size_t)BB * NH * SQ * SQ];     // 0.54 GB

// ---------------- helpers ------------------------------------------------------
__device__ __forceinline__ uint32_t smem_u32(const void* p) {
    uint32_t a;
    asm("{ .reg .u64 t; cvta.to.shared.u64 t, %1; cvt.u32.u64 %0, t; }" : "=r"(a) : "l"(p));
    return a;
}
__device__ __forceinline__ void cp_async16(uint32_t dst, const void* src) {
    asm volatile("cp.async.cg.shared.global [%0], [%1], 16;" :: "r"(dst), "l"(src) : "memory");
}
#define CP_COMMIT() asm volatile("cp.async.commit_group;" ::: "memory")
#define CP_WAIT1()  asm volatile("cp.async.wait_group 1;" ::: "memory")

__device__ __forceinline__ void split_h2(float2 f, uint32_t& hi, uint32_t& lo) {
    __half2 h = __float22half2_rn(f);
    float2 back = __half22float2(h);
    __half2 l = __float22half2_rn(make_float2(f.x - back.x, f.y - back.y));
    hi = *(uint32_t*)&h;
    lo = *(uint32_t*)&l;
}
__device__ __forceinline__ uint32_t pack_h2(float a, float b) {
    __half2 h = __float22half2_rn(make_float2(a, b));
    return *(uint32_t*)&h;
}
__device__ __forceinline__ void mma_f16(float* c, const uint32_t* a, const uint32_t* b) {
    asm volatile(
        "mma.sync.aligned.m16n8k16.row.col.f32.f16.f16.f32 "
        "{%0,%1,%2,%3}, {%4,%5,%6,%7}, {%8,%9}, {%0,%1,%2,%3};"
        : "+f"(c[0]), "+f"(c[1]), "+f"(c[2]), "+f"(c[3])
        : "r"(a[0]), "r"(a[1]), "r"(a[2]), "r"(a[3]), "r"(b[0]), "r"(b[1]));
}
__device__ __forceinline__ int inv_pair(int p) { return ((p & 3) << 1) | (p >> 2); }

// ---------------- prep: x split + 5 weight transpose/splits --------------------
__global__ void prep_kernel(const float* __restrict__ x,
                            const float* __restrict__ Wd, const float* __restrict__ Wuk,
                            const float* __restrict__ Wuv, const float* __restrict__ Wq,
                            const float* __restrict__ Wo)
{
    const int z = blockIdx.z;
    if (z == 0) {
        const int tid = threadIdx.y * 32 + threadIdx.x;
        long long base = ((long long)blockIdx.y * 64 + blockIdx.x) * 256 + tid;
        const long long tot = (long long)MTOT * DM / 2;
        for (long long i2 = base; i2 < tot; i2 += (long long)4096 * 256) {
            int d2 = (int)(i2 & (DM / 2 - 1));
            long long row = i2 >> 10;
            int d2p = (d2 & ~7) | inv_pair(d2 & 7);
            float2 v = ((const float2*)x)[i2];
            uint32_t h, l;
            split_h2(v, h, l);
            ((uint32_t*)g_xhi)[row * (DM / 2) + d2p] = h;
            ((uint32_t*)g_xlo)[row * (DM / 2) + d2p] = l;
        }
        return;
    }
    const float* in; __half *hi, *lo; int Cc, R;
    if      (z == 1) { in = Wd;  hi = g_wdh;  lo = g_wdl;  Cc = DL; R = DM; }
    else if (z == 2) { in = Wuk; hi = g_wukh; lo = g_wukl; Cc = DM; R = DL; }
    else if (z == 3) { in = Wuv; hi = g_wuvh; lo = g_wuvl; Cc = DM; R = DL; }
    else if (z == 4) { in = Wq;  hi = g_wqh;  lo = g_wql;  Cc = DM; R = DM; }
    else             { in = Wo;  hi = g_woh;  lo = g_wol;  Cc = DM; R = DM; }
    const int c0 = blockIdx.x * 32, r0 = blockIdx.y * 32;
    if (c0 >= Cc || r0 >= R) return;

    __shared__ float t[32][33];
#pragma unroll
    for (int i = threadIdx.y; i < 32; i += 8)
        t[i][threadIdx.x] = in[(long long)(r0 + i) * Cc + c0 + threadIdx.x];
    __syncthreads();
    const int e = r0 + threadIdx.x;
    const int p = e >> 1, bo = e & 1;
    const int pe = (((p & ~7) | inv_pair(p & 7)) << 1) | bo;
#pragma unroll
    for (int i = threadIdx.y; i < 32; i += 8) {
        float v = t[threadIdx.x][i];
        __half h = __float2half_rn(v);
        __half l = __float2half_rn(v - __half2float(h));
        hi[(long long)(c0 + i) * R + pe] = h;
        lo[(long long)(c0 + i) * R + pe] = l;
    }
}

// ---------------- fp16 hi/lo GEMM core (batched) -------------------------------
// TERMS==3: D = (Ah+Al) @ (Bh+Bl)^T  (drops Al*Bl)
// TERMS==2: D = Ah @ (Bh+Bl)^T      (A single fp16)
// Output: fp32 Cf, or split Chi/Clo (local-column pair-permuted), or V^T split.
#define BK 32
#define AROW 80
#define ARR (128 * AROW)
#define HSTAGE (4 * ARR)
#define SMEM_HGEMM (2 * HSTAGE)         // 81920

template<int TERMS>
__global__ __launch_bounds__(256, 2)
void hgemm(const __half* __restrict__ Ah, const __half* __restrict__ Al,
           const __half* __restrict__ Bh, const __half* __restrict__ Bl,
           float* __restrict__ Cf, __half* __restrict__ Chi, __half* __restrict__ Clo,
           __half* __restrict__ VtHi, __half* __restrict__ VtLo,
           const float* __restrict__ bias,
           int K, int lda, int ldb, int ldc, int nInner,
           long long aOut, long long aIn,
           long long bOut, long long bIn,
           long long cOut, long long cIn, float post)
{
    extern __shared__ char sm[];
    const uint32_t smb = smem_u32(sm);
    const int tid = threadIdx.x, wid = tid >> 5, lane = tid & 31;
    const int qr = lane >> 2, qc = lane & 3;
    const int warpM = (wid & 1) * 64, warpN = (wid >> 1) * 32;
    const int m0 = blockIdx.y * 128, n0 = blockIdx.x * 128;

    const int z = blockIdx.z;
    const long long zo = z / nInner, zi = z % nInner;
    Ah += zo * aOut + zi * aIn;
    Al += zo * aOut + zi * aIn;
    Bh += zo * bOut + zi * bIn;
    Bl += zo * bOut + zi * bIn;
    const long long coff = zo * cOut + zi * cIn;
    if (Cf)  Cf  += coff;
    if (Chi) { Chi += coff; Clo += coff; }

    const __half* A0 = Ah + (long long)m0 * lda;
    const __half* A1 = Al + (long long)m0 * lda;
    const __half* B0 = Bh + (long long)n0 * ldb;
    const __half* B1 = Bl + (long long)n0 * ldb;

    float acc[4][4][4];
#pragma unroll
    for (int mi = 0; mi < 4; mi++)
#pragma unroll
        for (int ni = 0; ni < 4; ni++)
#pragma unroll
            for (int t = 0; t < 4; t++) acc[mi][ni][t] = 0.0f;

    auto load_stage = [&](int t, int s) {
        const int k0 = t * BK;
        uint32_t base = smb + s * HSTAGE;
#pragma unroll
        for (int j = 0; j < 2; j++) {
            int g = tid + j * 256;
            int r = g >> 2, c = g & 3;
            uint32_t off = (uint32_t)(r * AROW + c * 16);
            cp_async16(base + off,           A0 + (long long)r * lda + k0 + c * 8);
            if (TERMS == 3)
                cp_async16(base + ARR + off, A1 + (long long)r * lda + k0 + c * 8);
            cp_async16(base + 2 * ARR + off, B0 + (long long)r * ldb + k0 + c * 8);
            cp_async16(base + 3 * ARR + off, B1 + (long long)r * ldb + k0 + c * 8);
        }
    };

    const int nk = K / BK;
    load_stage(0, 0); CP_COMMIT();
    load_stage(1, 1); CP_COMMIT();

    for (int i = 0; i < nk; i++) {
        CP_WAIT1();
        __syncthreads();
        const char* s = sm + (i & 1) * HSTAGE;
#pragma unroll
        for (int kk = 0; kk < 2; kk++) {
            uint32_t aH[4][4], aL[4][4], bH[4][2], bL[4][2];
#pragma unroll
            for (int mi = 0; mi < 4; mi++) {
                int row = warpM + mi * 16 + qr;
                uint2 v0 = *(const uint2*)(s + row * AROW + kk * 32 + qc * 8);
                uint2 v1 = *(const uint2*)(s + (row + 8) * AROW + kk * 32 + qc * 8);
                aH[mi][0] = v0.x; aH[mi][2] = v0.y; aH[mi][1] = v1.x; aH[mi][3] = v1.y;
                if (TERMS == 3) {
                    uint2 w0 = *(const uint2*)(s + ARR + row * AROW + kk * 32 + qc * 8);
                    uint2 w1 = *(const uint2*)(s + ARR + (row + 8) * AROW + kk * 32 + qc * 8);
                    aL[mi][0] = w0.x; aL[mi][2] = w0.y; aL[mi][1] = w1.x; aL[mi][3] = w1.y;
                }
            }
#pragma unroll
            for (int ni = 0; ni < 4; ni++) {
                int col = warpN + ni * 8 + qr;
                uint2 v = *(const uint2*)(s + 2 * ARR + col * AROW + kk * 32 + qc * 8);
                bH[ni][0] = v.x; bH[ni][1] = v.y;
                uint2 w = *(const uint2*)(s + 3 * ARR + col * AROW + kk * 32 + qc * 8);
                bL[ni][0] = w.x; bL[ni][1] = w.y;
            }
#pragma unroll
            for (int mi = 0; mi < 4; mi++)
#pragma unroll
                for (int ni = 0; ni < 4; ni++) {
                    if (TERMS == 3) mma_f16(acc[mi][ni], aL[mi], bH[ni]);
                    mma_f16(acc[mi][ni], aH[mi], bL[ni]);
                    mma_f16(acc[mi][ni], aH[mi], bH[ni]);
                }
        }
        __syncthreads();
        if (i + 2 < nk) load_stage(i + 2, i & 1);
        CP_COMMIT();
    }

    if (VtHi) {
        __syncthreads();
        float* tile = (float*)sm;   // [128][132]
#pragma unroll
        for (int mi = 0; mi < 4; mi++)
#pragma unroll
            for (int ni = 0; ni < 4; ni++) {
                int rl = warpM + mi * 16 + qr;
                int cl = warpN + ni * 8 + qc * 2;
                float2 bv = *(const float2*)(bias + n0 + cl);
                tile[rl * 132 + cl]       = acc[mi][ni][0] + bv.x;
                tile[rl * 132 + cl + 1]   = acc[mi][ni][1] + bv.y;
                tile[(rl + 8) * 132 + cl]     = acc[mi][ni][2] + bv.x;
                tile[(rl + 8) * 132 + cl + 1] = acc[mi][ni][3] + bv.y;
            }
        __syncthreads();
        const int h = n0 >> 7;
        const int bb = m0 >> 11;
        const int s0g = m0 & (SQ - 1);
        const int dl = tid >> 1, sh = (tid & 1) * 64;
        long long base = ((long long)(bb * NH + h) * DH + dl) * SQ + s0g + sh;
#pragma unroll
        for (int pp = 0; pp < 32; pp++) {
            int e = 2 * pp;
            int g = e >> 4, q = pp & 7;
            int off = g * 16 + inv_pair(q) * 2;
            float v0 = tile[(sh + e) * 132 + dl];
            float v1 = tile[(sh + e + 1) * 132 + dl];
            uint32_t hh, ll;
            split_h2(make_float2(v0, v1), hh, ll);
            *(uint32_t*)(VtHi + base + off) = hh;
            *(uint32_t*)(VtLo + base + off) = ll;
        }
        return;
    }

#pragma unroll
    for (int mi = 0; mi < 4; mi++) {
#pragma unroll
        for (int ni = 0; ni < 4; ni++) {
            int row = m0 + warpM + mi * 16 + qr;
            int colb = n0 + warpN + ni * 8;
            float2 bv = make_float2(0.f, 0.f);
            if (bias) bv = *(const float2*)(bias + colb + qc * 2);
            float2 v0 = make_float2((acc[mi][ni][0] + bv.x) * post, (acc[mi][ni][1] + bv.y) * post);
            float2 v1 = make_float2((acc[mi][ni][2] + bv.x) * post, (acc[mi][ni][3] + bv.y) * post);
            if (Cf) {
                *(float2*)(Cf + (long long)row * ldc + colb + qc * 2) = v0;
                *(float2*)(Cf + (long long)(row + 8) * ldc + colb + qc * 2) = v1;
            }
            if (Chi) {
                int p = (colb >> 1) + qc;
                int pp = (p & ~7) | inv_pair(p & 7);
                uint32_t h, l;
                split_h2(v0, h, l);
                ((uint32_t*)Chi)[(long long)row * (ldc >> 1) + pp] = h;
                ((uint32_t*)Clo)[(long long)row * (ldc >> 1) + pp] = l;
                split_h2(v1, h, l);
                ((uint32_t*)Chi)[(long long)(row + 8) * (ldc >> 1) + pp] = h;
                ((uint32_t*)Clo)[(long long)(row + 8) * (ldc >> 1) + pp] = l;
            }
        }
    }
}

// ---------------- row softmax: S fp32 -> P fp16 (pair-permuted cols) -----------
__launch_bounds__(256)
__global__ void softmax_kernel(const float* __restrict__ S, __half* __restrict__ P)
{
    const long long row = blockIdx.x;
    const float* s = S + row * SQ;
    uint32_t* p = (uint32_t*)P + row * (SQ / 2);
    const int tid = threadIdx.x;

    float4 v1 = ((const float4*)s)[tid];
    float4 v2 = ((const float4*)s)[256 + tid];
    float m = fmaxf(fmaxf(fmaxf(v1.x, v1.y), fmaxf(v1.z, v1.w)),
                    fmaxf(fmaxf(v2.x, v2.y), fmaxf(v2.z, v2.w)));
    __shared__ float red[256];
    red[tid] = m; __syncthreads();
    for (int st = 128; st > 0; st >>= 1) { if (tid < st) red[tid] = fmaxf(red[tid], red[tid + st]); __syncthreads(); }
    const float rowmax = red[0]; __syncthreads();

    v1.x = __expf(v1.x - rowmax); v1.y = __expf(v1.y - rowmax);
    v1.z = __expf(v1.z - rowmax); v1.w = __expf(v1.w - rowmax);
    v2.x = __expf(v2.x - rowmax); v2.y = __expf(v2.y - rowmax);
    v2.z = __expf(v2.z - rowmax); v2.w = __expf(v2.w - rowmax);
    float s8 = (v1.x + v1.y) + (v1.z + v1.w) + (v2.x + v2.y) + (v2.z + v2.w);
    red[tid] = s8; __syncthreads();
    for (int st = 128; st > 0; st >>= 1) { if (tid < st) red[tid] += red[tid + st]; __syncthreads(); }
    const float inv = 1.0f / red[0];

    // pairs: this thread owns pair indices 2*tid, 2*tid+1, 512+2*tid, 512+2*tid+1
    int pi0 = 2 * tid;
    int pp0 = (pi0 & ~7) | inv_pair(pi0 & 7);
    int pp1 = ((pi0 + 1) & ~7) | inv_pair((pi0 + 1) & 7);
    int pi2 = 512 + 2 * tid;
    int pp2 = (pi2 & ~7) | inv_pair(pi2 & 7);
    int pp3 = ((pi2 + 1) & ~7) | inv_pair((pi2 + 1) & 7);
    p[pp0] = pack_h2(v1.x * inv, v1.y * inv);
    p[pp1] = pack_h2(v1.z * inv, v1.w * inv);
    p[pp2] = pack_h2(v2.x * inv, v2.y * inv);
    p[pp3] = pack_h2(v2.z * inv, v2.w * inv);
}

// ---------------- launch -------------------------------------------------------
extern "C" void kernel_launch(void* const* d_in, const int* in_sizes, int n_in,
                              void* d_out, int out_size)
{
    const float* x      = (const float*)d_in[0];
    const float* W_down = (const float*)d_in[1];
    const float* b_down = (const float*)d_in[2];
    const float* W_uk   = (const float*)d_in[3];
    const float* b_uk   = (const float*)d_in[4];
    const float* W_uv   = (const float*)d_in[5];
    const float* b_uv   = (const float*)d_in[6];
    const float* W_q    = (const float*)d_in[7];
    const float* b_q    = (const float*)d_in[8];
    const float* W_o    = (const float*)d_in[9];
    const float* b_o    = (const float*)d_in[10];
    float* out = (float*)d_out;

    void *pa;
    cudaGetSymbolAddress(&pa, g_xhi);   __half* xhi = (__half*)pa;
    cudaGetSymbolAddress(&pa, g_xlo);   __half* xlo = (__half*)pa;
    cudaGetSymbolAddress(&pa, g_lathi); __half* lathi = (__half*)pa;
    cudaGetSymbolAddress(&pa, g_latlo); __half* latlo = (__half*)pa;
    cudaGetSymbolAddress(&pa, g_khi);   __half* khi = (__half*)pa;
    cudaGetSymbolAddress(&pa, g_klo);   __half* klo = (__half*)pa;
    cudaGetSymbolAddress(&pa, g_qhi);   __half* qhi = (__half*)pa;
    cudaGetSymbolAddress(&pa, g_qlo);   __half* qlo = (__half*)pa;
    cudaGetSymbolAddress(&pa, g_ctxhi); __half* ctxhi = (__half*)pa;
    cudaGetSymbolAddress(&pa, g_ctxlo); __half* ctxlo = (__half*)pa;
    cudaGetSymbolAddress(&pa, g_vthi);  __half* vthi = (__half*)pa;
    cudaGetSymbolAddress(&pa, g_vtlo);  __half* vtlo = (__half*)pa;
    cudaGetSymbolAddress(&pa, g_S);     float*  Sbuf = (float*)pa;
    cudaGetSymbolAddress(&pa, g_P);     __half* Pbuf = (__half*)pa;
    __half *wdh, *wdl, *wukh, *wukl, *wuvh, *wuvl, *wqh, *wql, *woh, *wol;
    cudaGetSymbolAddress(&pa, g_wdh);  wdh  = (__half*)pa;
    cudaGetSymbolAddress(&pa, g_wdl);  wdl  = (__half*)pa;
    cudaGetSymbolAddress(&pa, g_wukh); wukh = (__half*)pa;
    cudaGetSymbolAddress(&pa, g_wukl); wukl = (__half*)pa;
    cudaGetSymbolAddress(&pa, g_wuvh); wuvh = (__half*)pa;
    cudaGetSymbolAddress(&pa, g_wuvl); wuvl = (__half*)pa;
    cudaGetSymbolAddress(&pa, g_wqh);  wqh  = (__half*)pa;
    cudaGetSymbolAddress(&pa, g_wql);  wql  = (__half*)pa;
    cudaGetSymbolAddress(&pa, g_woh);  woh  = (__half*)pa;
    cudaGetSymbolAddress(&pa, g_wol);  wol  = (__half*)pa;

    static bool attr_set = false;
    if (!attr_set) {
        cudaFuncSetAttribute(hgemm<3>, cudaFuncAttributeMaxDynamicSharedMemorySize, SMEM_HGEMM);
        cudaFuncSetAttribute(hgemm<2>, cudaFuncAttributeMaxDynamicSharedMemorySize, SMEM_HGEMM);
        attr_set = true;
    }

    const float inv_sqrt_dh = 0.08838834764831845f;
    dim3 blk(256);

    // 0) prep: x split + weight transposes
    prep_kernel<<<dim3(64, 64, 6), dim3(32, 8)>>>(x, W_down, W_uk, W_uv, W_q, W_o);

    // 1) q = (x @ W_q + b_q)/sqrt(DH) -> split Q
    hgemm<3><<<dim3(DM/128, MTOT/128, 1), blk, SMEM_HGEMM>>>(
        xhi, xlo, wqh, wql, nullptr, qhi, qlo, nullptr, nullptr, b_q,
        DM, DM, DM, DM, 1, 0,0,0,0,0,0, inv_sqrt_dh);

    // 2) latents -> split lat
    hgemm<3><<<dim3(DL/128, MTOT/128, 1), blk, SMEM_HGEMM>>>(
        xhi, xlo, wdh, wdl, nullptr, lathi, latlo, nullptr, nullptr, b_down,
        DM, DM, DM, DL, 1, 0,0,0,0,0,0, 1.0f);

    // 3) keys -> split K
    hgemm<3><<<dim3(DM/128, MTOT/128, 1), blk, SMEM_HGEMM>>>(
        lathi, latlo, wukh, wukl, nullptr, khi, klo, nullptr, nullptr, b_uk,
        DL, DL, DL, DM, 1, 0,0,0,0,0,0, 1.0f);

    // 4) values -> V^T split (fused transpose)
    hgemm<3><<<dim3(DM/128, MTOT/128, 1), blk, SMEM_HGEMM>>>(
        lathi, latlo, wuvh, wuvl, nullptr, nullptr, nullptr, vthi, vtlo, b_uv,
        DL, DL, DL, DM, 1, 0,0,0,0,0,0, 1.0f);

    // 5) S[bh] = Q_bh @ K_bh^T  (scale baked into Q)
    hgemm<3><<<dim3(SQ/128, SQ/128, BB*NH), blk, SMEM_HGEMM>>>(
        qhi, qlo, khi, klo, Sbuf, nullptr, nullptr, nullptr, nullptr, nullptr,
        DH, DM, DM, SQ, NH,
        (long long)SQ * DM, (long long)DH,
        (long long)SQ * DM, (long long)DH,
        (long long)NH * SQ * SQ, (long long)SQ * SQ, 1.0f);

    // 6) softmax: S fp32 -> P fp16 (pair-permuted)
    softmax_kernel<<<BB * NH * SQ, 256>>>(Sbuf, Pbuf);

    // 7) ctx[bh] = P_bh @ Vt_bh^T  -> split ctx with head column offset
    hgemm<2><<<dim3(DH/128, SQ/128, BB*NH), blk, SMEM_HGEMM>>>(
        Pbuf, Pbuf, vthi, vtlo, nullptr, ctxhi, ctxlo, nullptr, nullptr, nullptr,
        SQ, SQ, SQ, DM, NH,
        (long long)NH * SQ * SQ, (long long)SQ * SQ,
        (long long)NH * DH * SQ, (long long)DH * SQ,
        (long long)SQ * DM, (long long)DH, 1.0f);

    // 8) out = ctx @ W_o + b_o
    hgemm<3><<<dim3(DM/128, MTOT/128, 1), blk, SMEM_HGEMM>>>(
        ctxhi, ctxlo, woh, wol, out, nullptr, nullptr, nullptr, nullptr, b_o,
        DM, DM, DM, DM, 1, 0,0,0,0,0,0, 1.0f);
}

// round 11
// speedup vs baseline: 1.0745x; 1.0745x over previous
#include <cuda_runtime.h>
#include <cuda_fp16.h>
#include <math.h>
#include <stdint.h>

#define SQ   2048
#define DM   2048
#define DH   128
#define NH   16
#define DL   512
#define BB   4
#define MTOT (BB*SQ)

// ---------------- scratch ------------------------------------------------------
__device__ __half g_xhi[(size_t)MTOT * DM],  g_xlo[(size_t)MTOT * DM];
__device__ __half g_lathi[(size_t)MTOT * DL], g_latlo[(size_t)MTOT * DL];
__device__ __half g_khi[(size_t)MTOT * DM],  g_klo[(size_t)MTOT * DM];
__device__ __half g_qhi[(size_t)MTOT * DM],  g_qlo[(size_t)MTOT * DM];
__device__ __half g_ctxhi[(size_t)MTOT * DM], g_ctxlo[(size_t)MTOT * DM];
__device__ __half g_vthi[(size_t)BB * NH * DH * SQ], g_vtlo[(size_t)BB * NH * DH * SQ];
__device__ __half g_wdh[(size_t)DM * DL], g_wdl[(size_t)DM * DL];
__device__ __half g_wukh[(size_t)DL * DM], g_wukl[(size_t)DL * DM];
__device__ __half g_wuvh[(size_t)DL * DM], g_wuvl[(size_t)DL * DM];
__device__ __half g_wqh[(size_t)DM * DM],  g_wql[(size_t)DM * DM];
__device__ __half g_woh[(size_t)DM * DM],  g_wol[(size_t)DM * DM];

// ---------------- helpers ------------------------------------------------------
__device__ __forceinline__ uint32_t smem_u32(const void* p) {
    uint32_t a;
    asm("{ .reg .u64 t; cvta.to.shared.u64 t, %1; cvt.u32.u64 %0, t; }" : "=r"(a) : "l"(p));
    return a;
}
__device__ __forceinline__ void cp_async16(uint32_t dst, const void* src) {
    asm volatile("cp.async.cg.shared.global [%0], [%1], 16;" :: "r"(dst), "l"(src) : "memory");
}
#define CP_COMMIT() asm volatile("cp.async.commit_group;" ::: "memory")
#define CP_WAIT1()  asm volatile("cp.async.wait_group 1;" ::: "memory")

__device__ __forceinline__ void split_h2(float2 f, uint32_t& hi, uint32_t& lo) {
    __half2 h = __float22half2_rn(f);
    float2 back = __half22float2(h);
    __half2 l = __float22half2_rn(make_float2(f.x - back.x, f.y - back.y));
    hi = *(uint32_t*)&h;
    lo = *(uint32_t*)&l;
}
__device__ __forceinline__ uint32_t pack_h2(float a, float b) {
    __half2 h = __float22half2_rn(make_float2(a, b));
    return *(uint32_t*)&h;
}
__device__ __forceinline__ void mma_f16(float* c, const uint32_t* a, const uint32_t* b) {
    asm volatile(
        "mma.sync.aligned.m16n8k16.row.col.f32.f16.f16.f32 "
        "{%0,%1,%2,%3}, {%4,%5,%6,%7}, {%8,%9}, {%0,%1,%2,%3};"
        : "+f"(c[0]), "+f"(c[1]), "+f"(c[2]), "+f"(c[3])
        : "r"(a[0]), "r"(a[1]), "r"(a[2]), "r"(a[3]), "r"(b[0]), "r"(b[1]));
}
__device__ __forceinline__ int inv_pair(int p) { return ((p & 3) << 1) | (p >> 2); }

// ---------------- prep: x split + 5 weight transpose/splits --------------------
__global__ void prep_kernel(const float* __restrict__ x,
                            const float* __restrict__ Wd, const float* __restrict__ Wuk,
                            const float* __restrict__ Wuv, const float* __restrict__ Wq,
                            const float* __restrict__ Wo)
{
    const int z = blockIdx.z;
    if (z == 0) {
        const int tid = threadIdx.y * 32 + threadIdx.x;
        long long base = ((long long)blockIdx.y * 64 + blockIdx.x) * 256 + tid;
        const long long tot = (long long)MTOT * DM / 2;
        for (long long i2 = base; i2 < tot; i2 += (long long)4096 * 256) {
            int d2 = (int)(i2 & (DM / 2 - 1));
            long long row = i2 >> 10;
            int d2p = (d2 & ~7) | inv_pair(d2 & 7);
            float2 v = ((const float2*)x)[i2];
            uint32_t h, l;
            split_h2(v, h, l);
            ((uint32_t*)g_xhi)[row * (DM / 2) + d2p] = h;
            ((uint32_t*)g_xlo)[row * (DM / 2) + d2p] = l;
        }
        return;
    }
    const float* in; __half *hi, *lo; int Cc, R;
    if      (z == 1) { in = Wd;  hi = g_wdh;  lo = g_wdl;  Cc = DL; R = DM; }
    else if (z == 2) { in = Wuk; hi = g_wukh; lo = g_wukl; Cc = DM; R = DL; }
    else if (z == 3) { in = Wuv; hi = g_wuvh; lo = g_wuvl; Cc = DM; R = DL; }
    else if (z == 4) { in = Wq;  hi = g_wqh;  lo = g_wql;  Cc = DM; R = DM; }
    else             { in = Wo;  hi = g_woh;  lo = g_wol;  Cc = DM; R = DM; }
    const int c0 = blockIdx.x * 32, r0 = blockIdx.y * 32;
    if (c0 >= Cc || r0 >= R) return;

    __shared__ float t[32][33];
#pragma unroll
    for (int i = threadIdx.y; i < 32; i += 8)
        t[i][threadIdx.x] = in[(long long)(r0 + i) * Cc + c0 + threadIdx.x];
    __syncthreads();
    const int e = r0 + threadIdx.x;
    const int p = e >> 1, bo = e & 1;
    const int pe = (((p & ~7) | inv_pair(p & 7)) << 1) | bo;
#pragma unroll
    for (int i = threadIdx.y; i < 32; i += 8) {
        float v = t[threadIdx.x][i];
        __half h = __float2half_rn(v);
        __half l = __float2half_rn(v - __half2float(h));
        hi[(long long)(c0 + i) * R + pe] = h;
        lo[(long long)(c0 + i) * R + pe] = l;
    }
}

// ---------------- pre-split fp16 hi/lo GEMM ------------------------------------
#define BK 32
#define AROW 80
#define ARR (128 * AROW)
#define HSTAGE (4 * ARR)
#define SMEM_HGEMM (2 * HSTAGE)         // 81920

__global__ __launch_bounds__(256, 2)
void hgemm(const __half* __restrict__ Ah, const __half* __restrict__ Al,
           const __half* __restrict__ Bh, const __half* __restrict__ Bl,
           float* __restrict__ Cf, __half* __restrict__ Chi, __half* __restrict__ Clo,
           __half* __restrict__ VtHi, __half* __restrict__ VtLo,
           const float* __restrict__ bias,
           int K, int lda, int ldb, int ldc, float post)
{
    extern __shared__ char sm[];
    const uint32_t smb = smem_u32(sm);
    const int tid = threadIdx.x, wid = tid >> 5, lane = tid & 31;
    const int qr = lane >> 2, qc = lane & 3;
    const int warpM = (wid & 1) * 64, warpN = (wid >> 1) * 32;
    const int m0 = blockIdx.y * 128, n0 = blockIdx.x * 128;

    const __half* A0 = Ah + (long long)m0 * lda;
    const __half* A1 = Al + (long long)m0 * lda;
    const __half* B0 = Bh + (long long)n0 * ldb;
    const __half* B1 = Bl + (long long)n0 * ldb;

    float acc[4][4][4];
#pragma unroll
    for (int mi = 0; mi < 4; mi++)
#pragma unroll
        for (int ni = 0; ni < 4; ni++)
#pragma unroll
            for (int t = 0; t < 4; t++) acc[mi][ni][t] = 0.0f;

    auto load_stage = [&](int t, int s) {
        const int k0 = t * BK;
        uint32_t base = smb + s * HSTAGE;
#pragma unroll
        for (int j = 0; j < 2; j++) {
            int g = tid + j * 256;
            int r = g >> 2, c = g & 3;
            uint32_t off = (uint32_t)(r * AROW + c * 16);
            cp_async16(base + off,           A0 + (long long)r * lda + k0 + c * 8);
            cp_async16(base + ARR + off,     A1 + (long long)r * lda + k0 + c * 8);
            cp_async16(base + 2 * ARR + off, B0 + (long long)r * ldb + k0 + c * 8);
            cp_async16(base + 3 * ARR + off, B1 + (long long)r * ldb + k0 + c * 8);
        }
    };

    const int nk = K / BK;
    load_stage(0, 0); CP_COMMIT();
    load_stage(1, 1); CP_COMMIT();

    for (int i = 0; i < nk; i++) {
        CP_WAIT1();
        __syncthreads();
        const char* s = sm + (i & 1) * HSTAGE;
#pragma unroll
        for (int kk = 0; kk < 2; kk++) {
            uint32_t aH[4][4], aL[4][4], bH[4][2], bL[4][2];
#pragma unroll
            for (int mi = 0; mi < 4; mi++) {
                int row = warpM + mi * 16 + qr;
                uint2 v0 = *(const uint2*)(s + row * AROW + kk * 32 + qc * 8);
                uint2 v1 = *(const uint2*)(s + (row + 8) * AROW + kk * 32 + qc * 8);
                aH[mi][0] = v0.x; aH[mi][2] = v0.y; aH[mi][1] = v1.x; aH[mi][3] = v1.y;
                uint2 w0 = *(const uint2*)(s + ARR + row * AROW + kk * 32 + qc * 8);
                uint2 w1 = *(const uint2*)(s + ARR + (row + 8) * AROW + kk * 32 + qc * 8);
                aL[mi][0] = w0.x; aL[mi][2] = w0.y; aL[mi][1] = w1.x; aL[mi][3] = w1.y;
            }
#pragma unroll
            for (int ni = 0; ni < 4; ni++) {
                int col = warpN + ni * 8 + qr;
                uint2 v = *(const uint2*)(s + 2 * ARR + col * AROW + kk * 32 + qc * 8);
                bH[ni][0] = v.x; bH[ni][1] = v.y;
                uint2 w = *(const uint2*)(s + 3 * ARR + col * AROW + kk * 32 + qc * 8);
                bL[ni][0] = w.x; bL[ni][1] = w.y;
            }
#pragma unroll
            for (int mi = 0; mi < 4; mi++)
#pragma unroll
                for (int ni = 0; ni < 4; ni++) {
                    mma_f16(acc[mi][ni], aL[mi], bH[ni]);
                    mma_f16(acc[mi][ni], aH[mi], bL[ni]);
                    mma_f16(acc[mi][ni], aH[mi], bH[ni]);
                }
        }
        __syncthreads();
        if (i + 2 < nk) load_stage(i + 2, i & 1);
        CP_COMMIT();
    }

    if (VtHi) {
        __syncthreads();
        float* tile = (float*)sm;   // [128][132]
#pragma unroll
        for (int mi = 0; mi < 4; mi++)
#pragma unroll
            for (int ni = 0; ni < 4; ni++) {
                int rl = warpM + mi * 16 + qr;
                int cl = warpN + ni * 8 + qc * 2;
                float2 bv = *(const float2*)(bias + n0 + cl);
                tile[rl * 132 + cl]       = acc[mi][ni][0] + bv.x;
                tile[rl * 132 + cl + 1]   = acc[mi][ni][1] + bv.y;
                tile[(rl + 8) * 132 + cl]     = acc[mi][ni][2] + bv.x;
                tile[(rl + 8) * 132 + cl + 1] = acc[mi][ni][3] + bv.y;
            }
        __syncthreads();
        const int h = n0 >> 7;
        const int bb = m0 >> 11;
        const int s0g = m0 & (SQ - 1);
        const int dl = tid >> 1, sh = (tid & 1) * 64;
        long long base = ((long long)(bb * NH + h) * DH + dl) * SQ + s0g + sh;
#pragma unroll
        for (int pp = 0; pp < 32; pp++) {
            int e = 2 * pp;
            int g = e >> 4, q = pp & 7;
            int off = g * 16 + inv_pair(q) * 2;
            float v0 = tile[(sh + e) * 132 + dl];
            float v1 = tile[(sh + e + 1) * 132 + dl];
            uint32_t hh, ll;
            split_h2(make_float2(v0, v1), hh, ll);
            *(uint32_t*)(VtHi + base + off) = hh;
            *(uint32_t*)(VtLo + base + off) = ll;
        }
        return;
    }

#pragma unroll
    for (int mi = 0; mi < 4; mi++) {
#pragma unroll
        for (int ni = 0; ni < 4; ni++) {
            int row = m0 + warpM + mi * 16 + qr;
            int colb = n0 + warpN + ni * 8;
            float2 bv = make_float2(0.f, 0.f);
            if (bias) bv = *(const float2*)(bias + colb + qc * 2);
            float2 v0 = make_float2((acc[mi][ni][0] + bv.x) * post, (acc[mi][ni][1] + bv.y) * post);
            float2 v1 = make_float2((acc[mi][ni][2] + bv.x) * post, (acc[mi][ni][3] + bv.y) * post);
            if (Cf) {
                *(float2*)(Cf + (long long)row * ldc + colb + qc * 2) = v0;
                *(float2*)(Cf + (long long)(row + 8) * ldc + colb + qc * 2) = v1;
            }
            if (Chi) {
                int p = (colb >> 1) + qc;
                int pp = (p & ~7) | inv_pair(p & 7);
                uint32_t h, l;
                split_h2(v0, h, l);
                ((uint32_t*)Chi)[(long long)row * (ldc >> 1) + pp] = h;
                ((uint32_t*)Clo)[(long long)row * (ldc >> 1) + pp] = l;
                split_h2(v1, h, l);
                ((uint32_t*)Chi)[(long long)(row + 8) * (ldc >> 1) + pp] = h;
                ((uint32_t*)Clo)[(long long)(row + 8) * (ldc >> 1) + pp] = l;
            }
        }
    }
}

// ---------------- fused flash attention: 512 threads, M=256, CHUNK=32 ----------
// 16 warps (4/SMSP, matching hgemm's proven warp density). Q resident in smem.
#define CHUNK 32
#define QROWB 272
#define KROWB 272
#define VROWB 80
#define SM_QH 0
#define SM_QL (256 * QROWB)              // 69632
#define KV0   (2 * 256 * QROWB)          // 139264
#define KVSTG (2 * 32 * KROWB + 128 * VROWB)   // 17408 + 10240 = 27648
#define FKH(s) (KV0 + (s) * KVSTG)
#define FKL(s) (KV0 + (s) * KVSTG + 32 * KROWB)
#define FV(s)  (KV0 + (s) * KVSTG + 64 * KROWB)
#define SMEM_FLASH (KV0 + 2 * KVSTG)     // 194560

__global__ __launch_bounds__(512, 1)
void flash_kernel(const __half* __restrict__ Qhi, const __half* __restrict__ Qlo,
                  const __half* __restrict__ Khi, const __half* __restrict__ Klo,
                  const __half* __restrict__ Vhi,
                  __half* __restrict__ Chi, __half* __restrict__ Clo)
{
    extern __shared__ char smc[];
    const uint32_t smb = smem_u32(smc);
    const int tid = threadIdx.x, wid = tid >> 5, lane = tid & 31;
    const int qr = lane >> 2, qc = lane & 3;
    const int bh = blockIdx.y, b = bh >> 4, h = bh & 15;
    const int q0 = blockIdx.x * 256;

    const long long qbase = (long long)(b * SQ + q0);

    // ---- stage Q hi/lo into smem (once): 256 rows x 128 dh ----
    {
        const __half* qh_g = Qhi + qbase * DM + h * DH;
        const __half* ql_g = Qlo + qbase * DM + h * DH;
        for (int g = tid; g < 4096; g += 512) {
            int r = g >> 4, c = g & 15;
            cp_async16(smb + SM_QH + r * QROWB + c * 16, qh_g + (long long)r * DM + c * 8);
            cp_async16(smb + SM_QL + r * QROWB + c * 16, ql_g + (long long)r * DM + c * 8);
        }
    }

    float accO[16][4];
#pragma unroll
    for (int t = 0; t < 16; t++)
#pragma unroll
        for (int c = 0; c < 4; c++) accO[t][c] = 0.0f;
    float mr0 = -INFINITY, mr1 = -INFINITY, lr0 = 0.0f, lr1 = 0.0f;

    const __half* kh_g = Khi + (long long)(b * SQ) * DM + h * DH;
    const __half* kl_g = Klo + (long long)(b * SQ) * DM + h * DH;
    const __half* vh_g = Vhi + (long long)bh * DH * SQ;

    auto loadKV = [&](int j, int s) {
        int s0 = j * CHUNK;
        {   // K hi + lo: 32 rows x 16 segs each
            int r = tid >> 4, c = tid & 15;     // tid < 512 -> r 0..31
            cp_async16(smb + FKH(s) + r * KROWB + c * 16, kh_g + (long long)(s0 + r) * DM + c * 8);
            cp_async16(smb + FKL(s) + r * KROWB + c * 16, kl_g + (long long)(s0 + r) * DM + c * 8);
        }
        {   // V: 128 dh-rows x 4 segs (32 s = 64B)
            int r = tid >> 2, c = tid & 3;      // r 0..127
            cp_async16(smb + FV(s) + r * VROWB + c * 16, vh_g + (long long)r * SQ + s0 + c * 8);
        }
    };

    loadKV(0, 0);       // group 0 = Q + KV0
    CP_COMMIT();

    const char* qhp = smc + SM_QH + (wid * 16 + qr) * QROWB;
    const char* qlp = smc + SM_QL + (wid * 16 + qr) * QROWB;

    const int NCH = SQ / CHUNK;   // 64
    for (int j = 0; j < NCH; j++) {
        if (j + 1 < NCH) loadKV(j + 1, (j + 1) & 1);
        CP_COMMIT();
        CP_WAIT1();                // Q + KV(j) complete; KV(j+1) in flight
        __syncthreads();
        const int st = j & 1;

        // ---- S = Q @ K^T (3-term), 32 keys = 4 n8-tiles ----
        float accS[4][4];
#pragma unroll
        for (int t = 0; t < 4; t++)
#pragma unroll
            for (int c = 0; c < 4; c++) accS[t][c] = 0.0f;
#pragma unroll
        for (int kk = 0; kk < 8; kk++) {
            uint32_t aH[4], aL[4];
            {
                uint2 v0 = *(const uint2*)(qhp + kk * 32 + qc * 8);
                uint2 v1 = *(const uint2*)(qhp + 8 * QROWB + kk * 32 + qc * 8);
                aH[0] = v0.x; aH[2] = v0.y; aH[1] = v1.x; aH[3] = v1.y;
                uint2 w0 = *(const uint2*)(qlp + kk * 32 + qc * 8);
                uint2 w1 = *(const uint2*)(qlp + 8 * QROWB + kk * 32 + qc * 8);
                aL[0] = w0.x; aL[2] = w0.y; aL[1] = w1.x; aL[3] = w1.y;
            }
#pragma unroll
            for (int t = 0; t < 4; t++) {
                uint2 bhv = *(const uint2*)(smc + FKH(st) + (8 * t + qr) * KROWB + kk * 32 + qc * 8);
                uint2 blv = *(const uint2*)(smc + FKL(st) + (8 * t + qr) * KROWB + kk * 32 + qc * 8);
                uint32_t bH[2] = {bhv.x, bhv.y}, bL[2] = {blv.x, blv.y};
                mma_f16(accS[t], aL, bH);
                mma_f16(accS[t], aH, bL);
                mma_f16(accS[t], aH, bH);
            }
        }

        // ---- online softmax (rescale only when max moves) ----
        float mx0 = -INFINITY, mx1 = -INFINITY;
#pragma unroll
        for (int t = 0; t < 4; t++) {
            mx0 = fmaxf(mx0, fmaxf(accS[t][0], accS[t][1]));
            mx1 = fmaxf(mx1, fmaxf(accS[t][2], accS[t][3]));
        }
        mx0 = fmaxf(mx0, __shfl_xor_sync(0xFFFFFFFFu, mx0, 1));
        mx0 = fmaxf(mx0, __shfl_xor_sync(0xFFFFFFFFu, mx0, 2));
        mx1 = fmaxf(mx1, __shfl_xor_sync(0xFFFFFFFFu, mx1, 1));
        mx1 = fmaxf(mx1, __shfl_xor_sync(0xFFFFFFFFu, mx1, 2));
        if (mx0 > mr0 || mx1 > mr1) {
            float mn0 = fmaxf(mr0, mx0), mn1 = fmaxf(mr1, mx1);
            float al0 = __expf(mr0 - mn0), al1 = __expf(mr1 - mn1);
            mr0 = mn0; mr1 = mn1;
            lr0 *= al0; lr1 *= al1;
#pragma unroll
            for (int t = 0; t < 16; t++) {
                accO[t][0] *= al0; accO[t][1] *= al0;
                accO[t][2] *= al1; accO[t][3] *= al1;
            }
        }
        uint32_t ph[4][2];
#pragma unroll
        for (int t = 0; t < 4; t++) {
            float p0 = __expf(accS[t][0] - mr0);
            float p1 = __expf(accS[t][1] - mr0);
            float p2 = __expf(accS[t][2] - mr1);
            float p3 = __expf(accS[t][3] - mr1);
            lr0 += p0 + p1;
            lr1 += p2 + p3;
            ph[t][0] = pack_h2(p0, p1);
            ph[t][1] = pack_h2(p2, p3);
        }

        // ---- O += P @ V (single fp16 V), k-dim 32 = 2 kk2 steps ----
#pragma unroll
        for (int kk2 = 0; kk2 < 2; kk2++) {
            uint32_t aH[4] = {ph[2 * kk2][0], ph[2 * kk2][1], ph[2 * kk2 + 1][0], ph[2 * kk2 + 1][1]};
#pragma unroll
            for (int t = 0; t < 16; t++) {
                uint2 vh2 = *(const uint2*)(smc + FV(st) + (8 * t + qr) * VROWB + kk2 * 32 + qc * 8);
                uint32_t bV[2] = {vh2.x, vh2.y};
                mma_f16(accO[t], aH, bV);
            }
        }
        __syncthreads();
    }

    // ---- epilogue: normalize, split, store ----
    lr0 += __shfl_xor_sync(0xFFFFFFFFu, lr0, 1);
    lr0 += __shfl_xor_sync(0xFFFFFFFFu, lr0, 2);
    lr1 += __shfl_xor_sync(0xFFFFFFFFu, lr1, 1);
    lr1 += __shfl_xor_sync(0xFFFFFFFFu, lr1, 2);
    const float i0 = 1.0f / lr0, i1 = 1.0f / lr1;
    const long long rowA = qbase + wid * 16 + qr;
#pragma unroll
    for (int t = 0; t < 16; t++) {
        int p = 64 * h + 4 * t + qc;
        int pp = (p & ~7) | inv_pair(p & 7);
        uint32_t hh, ll;
        split_h2(make_float2(accO[t][0] * i0, accO[t][1] * i0), hh, ll);
        ((uint32_t*)Chi)[rowA * (DM / 2) + pp] = hh;
        ((uint32_t*)Clo)[rowA * (DM / 2) + pp] = ll;
        split_h2(make_float2(accO[t][2] * i1, accO[t][3] * i1), hh, ll);
        ((uint32_t*)Chi)[(rowA + 8) * (DM / 2) + pp] = hh;
        ((uint32_t*)Clo)[(rowA + 8) * (DM / 2) + pp] = ll;
    }
}

// ---------------- launch -------------------------------------------------------
extern "C" void kernel_launch(void* const* d_in, const int* in_sizes, int n_in,
                              void* d_out, int out_size)
{
    const float* x      = (const float*)d_in[0];
    const float* W_down = (const float*)d_in[1];
    const float* b_down = (const float*)d_in[2];
    const float* W_uk   = (const float*)d_in[3];
    const float* b_uk   = (const float*)d_in[4];
    const float* W_uv   = (const float*)d_in[5];
    const float* b_uv   = (const float*)d_in[6];
    const float* W_q    = (const float*)d_in[7];
    const float* b_q    = (const float*)d_in[8];
    const float* W_o    = (const float*)d_in[9];
    const float* b_o    = (const float*)d_in[10];
    float* out = (float*)d_out;

    void *pa;
    cudaGetSymbolAddress(&pa, g_xhi);   __half* xhi = (__half*)pa;
    cudaGetSymbolAddress(&pa, g_xlo);   __half* xlo = (__half*)pa;
    cudaGetSymbolAddress(&pa, g_lathi); __half* lathi = (__half*)pa;
    cudaGetSymbolAddress(&pa, g_latlo); __half* latlo = (__half*)pa;
    cudaGetSymbolAddress(&pa, g_khi);   __half* khi = (__half*)pa;
    cudaGetSymbolAddress(&pa, g_klo);   __half* klo = (__half*)pa;
    cudaGetSymbolAddress(&pa, g_qhi);   __half* qhi = (__half*)pa;
    cudaGetSymbolAddress(&pa, g_qlo);   __half* qlo = (__half*)pa;
    cudaGetSymbolAddress(&pa, g_ctxhi); __half* ctxhi = (__half*)pa;
    cudaGetSymbolAddress(&pa, g_ctxlo); __half* ctxlo = (__half*)pa;
    cudaGetSymbolAddress(&pa, g_vthi);  __half* vthi = (__half*)pa;
    cudaGetSymbolAddress(&pa, g_vtlo);  __half* vtlo = (__half*)pa;
    __half *wdh, *wdl, *wukh, *wukl, *wuvh, *wuvl, *wqh, *wql, *woh, *wol;
    cudaGetSymbolAddress(&pa, g_wdh);  wdh  = (__half*)pa;
    cudaGetSymbolAddress(&pa, g_wdl);  wdl  = (__half*)pa;
    cudaGetSymbolAddress(&pa, g_wukh); wukh = (__half*)pa;
    cudaGetSymbolAddress(&pa, g_wukl); wukl = (__half*)pa;
    cudaGetSymbolAddress(&pa, g_wuvh); wuvh = (__half*)pa;
    cudaGetSymbolAddress(&pa, g_wuvl); wuvl = (__half*)pa;
    cudaGetSymbolAddress(&pa, g_wqh);  wqh  = (__half*)pa;
    cudaGetSymbolAddress(&pa, g_wql);  wql  = (__half*)pa;
    cudaGetSymbolAddress(&pa, g_woh);  woh  = (__half*)pa;
    cudaGetSymbolAddress(&pa, g_wol);  wol  = (__half*)pa;

    static bool attr_set = false;
    if (!attr_set) {
        cudaFuncSetAttribute(hgemm, cudaFuncAttributeMaxDynamicSharedMemorySize, SMEM_HGEMM);
        cudaFuncSetAttribute(flash_kernel, cudaFuncAttributeMaxDynamicSharedMemorySize, SMEM_FLASH);
        attr_set = true;
    }

    const float inv_sqrt_dh = 0.08838834764831845f;
    dim3 blk(256);

    // 0) prep
    prep_kernel<<<dim3(64, 64, 6), dim3(32, 8)>>>(x, W_down, W_uk, W_uv, W_q, W_o);

    // 1) q = (x @ W_q + b_q)/sqrt(DH) -> split Q
    hgemm<<<dim3(DM/128, MTOT/128), blk, SMEM_HGEMM>>>(
        xhi, xlo, wqh, wql, nullptr, qhi, qlo, nullptr, nullptr, b_q, DM, DM, DM, DM, inv_sqrt_dh);

    // 2) latents -> split lat
    hgemm<<<dim3(DL/128, MTOT/128), blk, SMEM_HGEMM>>>(
        xhi, xlo, wdh, wdl, nullptr, lathi, latlo, nullptr, nullptr, b_down, DM, DM, DM, DL, 1.0f);

    // 3) keys -> split K
    hgemm<<<dim3(DM/128, MTOT/128), blk, SMEM_HGEMM>>>(
        lathi, latlo, wukh, wukl, nullptr, khi, klo, nullptr, nullptr, b_uk, DL, DL, DL, DM, 1.0f);

    // 4) values -> V^T split (fused transpose)
    hgemm<<<dim3(DM/128, MTOT/128), blk, SMEM_HGEMM>>>(
        lathi, latlo, wuvh, wuvl, nullptr, nullptr, nullptr, vthi, vtlo, b_uv, DL, DL, DL, DM, 1.0f);

    // 5) flash attention (512 threads, M=256, CHUNK=32) -> split ctx
    flash_kernel<<<dim3(SQ/256, BB*NH), dim3(512), SMEM_FLASH>>>(
        qhi, qlo, khi, klo, vthi, ctxhi, ctxlo);

    // 6) out = ctx @ W_o + b_o
    hgemm<<<dim3(DM/128, MTOT/128), blk, SMEM_HGEMM>>>(
        ctxhi, ctxlo, woh, wol, out, nullptr, nullptr, nullptr, nullptr, b_o, DM, DM, DM, DM, 1.0f);
}

// round 12
// speedup vs baseline: 1.3408x; 1.2479x over previous
#include <cuda_runtime.h>
#include <cuda_fp16.h>
#include <math.h>
#include <stdint.h>

#define SQ   2048
#define DM   2048
#define DH   128
#define NH   16
#define DL   512
#define BB   4
#define MTOT (BB*SQ)

// ---------------- scratch ------------------------------------------------------
__device__ __half g_xhi[(size_t)MTOT * DM],  g_xlo[(size_t)MTOT * DM];
__device__ __half g_lathi[(size_t)MTOT * DL], g_latlo[(size_t)MTOT * DL];
__device__ __half g_khi[(size_t)MTOT * DM];
__device__ __half g_qhi[(size_t)MTOT * DM],  g_qlo[(size_t)MTOT * DM];
__device__ __half g_ctxhi[(size_t)MTOT * DM], g_ctxlo[(size_t)MTOT * DM];
__device__ __half g_vthi[(size_t)BB * NH * DH * SQ];
__device__ __half g_wdh[(size_t)DM * DL], g_wdl[(size_t)DM * DL];
__device__ __half g_wukh[(size_t)DL * DM], g_wukl[(size_t)DL * DM];
__device__ __half g_wuvh[(size_t)DL * DM], g_wuvl[(size_t)DL * DM];
__device__ __half g_wqh[(size_t)DM * DM],  g_wql[(size_t)DM * DM];
__device__ __half g_woh[(size_t)DM * DM],  g_wol[(size_t)DM * DM];

// ---------------- helpers ------------------------------------------------------
__device__ __forceinline__ uint32_t smem_u32(const void* p) {
    uint32_t a;
    asm("{ .reg .u64 t; cvta.to.shared.u64 t, %1; cvt.u32.u64 %0, t; }" : "=r"(a) : "l"(p));
    return a;
}
__device__ __forceinline__ void cp_async16(uint32_t dst, const void* src) {
    asm volatile("cp.async.cg.shared.global [%0], [%1], 16;" :: "r"(dst), "l"(src) : "memory");
}
#define CP_COMMIT() asm volatile("cp.async.commit_group;" ::: "memory")
#define CP_WAIT1()  asm volatile("cp.async.wait_group 1;" ::: "memory")

__device__ __forceinline__ void split_h2(float2 f, uint32_t& hi, uint32_t& lo) {
    __half2 h = __float22half2_rn(f);
    float2 back = __half22float2(h);
    __half2 l = __float22half2_rn(make_float2(f.x - back.x, f.y - back.y));
    hi = *(uint32_t*)&h;
    lo = *(uint32_t*)&l;
}
__device__ __forceinline__ uint32_t pack_h2(float a, float b) {
    __half2 h = __float22half2_rn(make_float2(a, b));
    return *(uint32_t*)&h;
}
__device__ __forceinline__ void mma_f16(float* c, const uint32_t* a, const uint32_t* b) {
    asm volatile(
        "mma.sync.aligned.m16n8k16.row.col.f32.f16.f16.f32 "
        "{%0,%1,%2,%3}, {%4,%5,%6,%7}, {%8,%9}, {%0,%1,%2,%3};"
        : "+f"(c[0]), "+f"(c[1]), "+f"(c[2]), "+f"(c[3])
        : "r"(a[0]), "r"(a[1]), "r"(a[2]), "r"(a[3]), "r"(b[0]), "r"(b[1]));
}
__device__ __forceinline__ int inv_pair(int p) { return ((p & 3) << 1) | (p >> 2); }

// ---------------- prep: x split + 5 weight transpose/splits --------------------
__global__ void prep_kernel(const float* __restrict__ x,
                            const float* __restrict__ Wd, const float* __restrict__ Wuk,
                            const float* __restrict__ Wuv, const float* __restrict__ Wq,
                            const float* __restrict__ Wo)
{
    const int z = blockIdx.z;
    if (z == 0) {
        const int tid = threadIdx.y * 32 + threadIdx.x;
        long long base = ((long long)blockIdx.y * 64 + blockIdx.x) * 256 + tid;
        const long long tot = (long long)MTOT * DM / 2;
        for (long long i2 = base; i2 < tot; i2 += (long long)4096 * 256) {
            int d2 = (int)(i2 & (DM / 2 - 1));
            long long row = i2 >> 10;
            int d2p = (d2 & ~7) | inv_pair(d2 & 7);
            float2 v = ((const float2*)x)[i2];
            uint32_t h, l;
            split_h2(v, h, l);
            ((uint32_t*)g_xhi)[row * (DM / 2) + d2p] = h;
            ((uint32_t*)g_xlo)[row * (DM / 2) + d2p] = l;
        }
        return;
    }
    const float* in; __half *hi, *lo; int Cc, R;
    if      (z == 1) { in = Wd;  hi = g_wdh;  lo = g_wdl;  Cc = DL; R = DM; }
    else if (z == 2) { in = Wuk; hi = g_wukh; lo = g_wukl; Cc = DM; R = DL; }
    else if (z == 3) { in = Wuv; hi = g_wuvh; lo = g_wuvl; Cc = DM; R = DL; }
    else if (z == 4) { in = Wq;  hi = g_wqh;  lo = g_wql;  Cc = DM; R = DM; }
    else             { in = Wo;  hi = g_woh;  lo = g_wol;  Cc = DM; R = DM; }
    const int c0 = blockIdx.x * 32, r0 = blockIdx.y * 32;
    if (c0 >= Cc || r0 >= R) return;

    __shared__ float t[32][33];
#pragma unroll
    for (int i = threadIdx.y; i < 32; i += 8)
        t[i][threadIdx.x] = in[(long long)(r0 + i) * Cc + c0 + threadIdx.x];
    __syncthreads();
    const int e = r0 + threadIdx.x;
    const int p = e >> 1, bo = e & 1;
    const int pe = (((p & ~7) | inv_pair(p & 7)) << 1) | bo;
#pragma unroll
    for (int i = threadIdx.y; i < 32; i += 8) {
        float v = t[threadIdx.x][i];
        __half h = __float2half_rn(v);
        __half l = __float2half_rn(v - __half2float(h));
        hi[(long long)(c0 + i) * R + pe] = h;
        lo[(long long)(c0 + i) * R + pe] = l;
    }
}

// ---------------- pre-split fp16 hi/lo GEMM ------------------------------------
#define BK 32
#define AROW 80
#define ARR (128 * AROW)
#define HSTAGE (4 * ARR)
#define SMEM_HGEMM (2 * HSTAGE)         // 81920

__global__ __launch_bounds__(256, 2)
void hgemm(const __half* __restrict__ Ah, const __half* __restrict__ Al,
           const __half* __restrict__ Bh, const __half* __restrict__ Bl,
           float* __restrict__ Cf, __half* __restrict__ Chi, __half* __restrict__ Clo,
           __half* __restrict__ VtHi,
           const float* __restrict__ bias,
           int K, int lda, int ldb, int ldc, float post)
{
    extern __shared__ char sm[];
    const uint32_t smb = smem_u32(sm);
    const int tid = threadIdx.x, wid = tid >> 5, lane = tid & 31;
    const int qr = lane >> 2, qc = lane & 3;
    const int warpM = (wid & 1) * 64, warpN = (wid >> 1) * 32;
    const int m0 = blockIdx.y * 128, n0 = blockIdx.x * 128;

    const __half* A0 = Ah + (long long)m0 * lda;
    const __half* A1 = Al + (long long)m0 * lda;
    const __half* B0 = Bh + (long long)n0 * ldb;
    const __half* B1 = Bl + (long long)n0 * ldb;

    float acc[4][4][4];
#pragma unroll
    for (int mi = 0; mi < 4; mi++)
#pragma unroll
        for (int ni = 0; ni < 4; ni++)
#pragma unroll
            for (int t = 0; t < 4; t++) acc[mi][ni][t] = 0.0f;

    auto load_stage = [&](int t, int s) {
        const int k0 = t * BK;
        uint32_t base = smb + s * HSTAGE;
#pragma unroll
        for (int j = 0; j < 2; j++) {
            int g = tid + j * 256;
            int r = g >> 2, c = g & 3;
            uint32_t off = (uint32_t)(r * AROW + c * 16);
            cp_async16(base + off,           A0 + (long long)r * lda + k0 + c * 8);
            cp_async16(base + ARR + off,     A1 + (long long)r * lda + k0 + c * 8);
            cp_async16(base + 2 * ARR + off, B0 + (long long)r * ldb + k0 + c * 8);
            cp_async16(base + 3 * ARR + off, B1 + (long long)r * ldb + k0 + c * 8);
        }
    };

    const int nk = K / BK;
    load_stage(0, 0); CP_COMMIT();
    load_stage(1, 1); CP_COMMIT();

    for (int i = 0; i < nk; i++) {
        CP_WAIT1();
        __syncthreads();
        const char* s = sm + (i & 1) * HSTAGE;
#pragma unroll
        for (int kk = 0; kk < 2; kk++) {
            uint32_t aH[4][4], aL[4][4], bH[4][2], bL[4][2];
#pragma unroll
            for (int mi = 0; mi < 4; mi++) {
                int row = warpM + mi * 16 + qr;
                uint2 v0 = *(const uint2*)(s + row * AROW + kk * 32 + qc * 8);
                uint2 v1 = *(const uint2*)(s + (row + 8) * AROW + kk * 32 + qc * 8);
                aH[mi][0] = v0.x; aH[mi][2] = v0.y; aH[mi][1] = v1.x; aH[mi][3] = v1.y;
                uint2 w0 = *(const uint2*)(s + ARR + row * AROW + kk * 32 + qc * 8);
                uint2 w1 = *(const uint2*)(s + ARR + (row + 8) * AROW + kk * 32 + qc * 8);
                aL[mi][0] = w0.x; aL[mi][2] = w0.y; aL[mi][1] = w1.x; aL[mi][3] = w1.y;
            }
#pragma unroll
            for (int ni = 0; ni < 4; ni++) {
                int col = warpN + ni * 8 + qr;
                uint2 v = *(const uint2*)(s + 2 * ARR + col * AROW + kk * 32 + qc * 8);
                bH[ni][0] = v.x; bH[ni][1] = v.y;
                uint2 w = *(const uint2*)(s + 3 * ARR + col * AROW + kk * 32 + qc * 8);
                bL[ni][0] = w.x; bL[ni][1] = w.y;
            }
#pragma unroll
            for (int mi = 0; mi < 4; mi++)
#pragma unroll
                for (int ni = 0; ni < 4; ni++) {
                    mma_f16(acc[mi][ni], aL[mi], bH[ni]);
                    mma_f16(acc[mi][ni], aH[mi], bL[ni]);
                    mma_f16(acc[mi][ni], aH[mi], bH[ni]);
                }
        }
        __syncthreads();
        if (i + 2 < nk) load_stage(i + 2, i & 1);
        CP_COMMIT();
    }

    if (VtHi) {
        // V^T epilogue: stage fp32 tile, write transposed single-fp16 (s permuted)
        __syncthreads();
        float* tile = (float*)sm;   // [128][132]
#pragma unroll
        for (int mi = 0; mi < 4; mi++)
#pragma unroll
            for (int ni = 0; ni < 4; ni++) {
                int rl = warpM + mi * 16 + qr;
                int cl = warpN + ni * 8 + qc * 2;
                float2 bv = *(const float2*)(bias + n0 + cl);
                tile[rl * 132 + cl]       = acc[mi][ni][0] + bv.x;
                tile[rl * 132 + cl + 1]   = acc[mi][ni][1] + bv.y;
                tile[(rl + 8) * 132 + cl]     = acc[mi][ni][2] + bv.x;
                tile[(rl + 8) * 132 + cl + 1] = acc[mi][ni][3] + bv.y;
            }
        __syncthreads();
        const int h = n0 >> 7;
        const int bb = m0 >> 11;
        const int s0g = m0 & (SQ - 1);
        const int dl = tid >> 1, sh = (tid & 1) * 64;
        long long base = ((long long)(bb * NH + h) * DH + dl) * SQ + s0g + sh;
#pragma unroll
        for (int pp = 0; pp < 32; pp++) {
            int e = 2 * pp;
            int g = e >> 4, q = pp & 7;
            int off = g * 16 + inv_pair(q) * 2;
            float v0 = tile[(sh + e) * 132 + dl];
            float v1 = tile[(sh + e + 1) * 132 + dl];
            *(uint32_t*)(VtHi + base + off) = pack_h2(v0, v1);
        }
        return;
    }

#pragma unroll
    for (int mi = 0; mi < 4; mi++) {
#pragma unroll
        for (int ni = 0; ni < 4; ni++) {
            int row = m0 + warpM + mi * 16 + qr;
            int colb = n0 + warpN + ni * 8;
            float2 bv = make_float2(0.f, 0.f);
            if (bias) bv = *(const float2*)(bias + colb + qc * 2);
            float2 v0 = make_float2((acc[mi][ni][0] + bv.x) * post, (acc[mi][ni][1] + bv.y) * post);
            float2 v1 = make_float2((acc[mi][ni][2] + bv.x) * post, (acc[mi][ni][3] + bv.y) * post);
            if (Cf) {
                *(float2*)(Cf + (long long)row * ldc + colb + qc * 2) = v0;
                *(float2*)(Cf + (long long)(row + 8) * ldc + colb + qc * 2) = v1;
            }
            if (Chi) {
                int p = (colb >> 1) + qc;
                int pp = (p & ~7) | inv_pair(p & 7);
                uint32_t h, l;
                split_h2(v0, h, l);
                ((uint32_t*)Chi)[(long long)row * (ldc >> 1) + pp] = h;
                if (Clo) ((uint32_t*)Clo)[(long long)row * (ldc >> 1) + pp] = l;
                split_h2(v1, h, l);
                ((uint32_t*)Chi)[(long long)(row + 8) * (ldc >> 1) + pp] = h;
                if (Clo) ((uint32_t*)Clo)[(long long)(row + 8) * (ldc >> 1) + pp] = l;
            }
        }
    }
}

// ---------------- fused flash attention (Q in regs, K single fp16) -------------
#define CHUNK 64
#define KROWB 272
#define VROWB 144
#define KVSTG (64 * KROWB + 128 * VROWB)   // 17408 + 18432 = 35840
#define FKH(s) ((s) * KVSTG)
#define FV(s)  ((s) * KVSTG + 64 * KROWB)
#define SMEM_FLASH (2 * KVSTG)             // 71680

__global__ __launch_bounds__(256)
void flash_kernel(const __half* __restrict__ Qhi, const __half* __restrict__ Qlo,
                  const __half* __restrict__ Khi, const __half* __restrict__ Vhi,
                  __half* __restrict__ Chi, __half* __restrict__ Clo)
{
    extern __shared__ char smc[];
    const uint32_t smb = smem_u32(smc);
    const int tid = threadIdx.x, wid = tid >> 5, lane = tid & 31;
    const int qr = lane >> 2, qc = lane & 3;
    const int bh = blockIdx.y, b = bh >> 4, h = bh & 15;
    const int q0 = blockIdx.x * 128;

    // ---- Q fragments in registers (pre-scaled, pre-split) ----
    const long long rowA = (long long)(b * SQ + q0 + wid * 16 + qr);
    const long long qoff = rowA * DM + h * DH;
    uint32_t qh[8][4], ql[8][4];
#pragma unroll
    for (int kk = 0; kk < 8; kk++) {
        uint2 v0 = *(const uint2*)(Qhi + qoff + kk * 16 + qc * 4);
        uint2 v1 = *(const uint2*)(Qhi + qoff + 8 * DM + kk * 16 + qc * 4);
        qh[kk][0] = v0.x; qh[kk][2] = v0.y; qh[kk][1] = v1.x; qh[kk][3] = v1.y;
        uint2 w0 = *(const uint2*)(Qlo + qoff + kk * 16 + qc * 4);
        uint2 w1 = *(const uint2*)(Qlo + qoff + 8 * DM + kk * 16 + qc * 4);
        ql[kk][0] = w0.x; ql[kk][2] = w0.y; ql[kk][1] = w1.x; ql[kk][3] = w1.y;
    }

    float accO[16][4];
#pragma unroll
    for (int t = 0; t < 16; t++)
#pragma unroll
        for (int c = 0; c < 4; c++) accO[t][c] = 0.0f;
    float mr0 = -INFINITY, mr1 = -INFINITY, lr0 = 0.0f, lr1 = 0.0f;

    const __half* kh_g = Khi + (long long)(b * SQ) * DM + h * DH;
    const __half* vh_g = Vhi + (long long)bh * DH * SQ;

    auto loadKV = [&](int j, int s) {
        int s0 = j * CHUNK;
        for (int g = tid; g < 1024; g += 256) {
            int r = g >> 4, c = g & 15;
            cp_async16(smb + FKH(s) + r * KROWB + c * 16, kh_g + (long long)(s0 + r) * DM + c * 8);
        }
        for (int g = tid; g < 1024; g += 256) {
            int r = g >> 3, c = g & 7;
            cp_async16(smb + FV(s) + r * VROWB + c * 16, vh_g + (long long)r * SQ + s0 + c * 8);
        }
    };

    loadKV(0, 0);
    CP_COMMIT();

    const int NCH = SQ / CHUNK;
    for (int j = 0; j < NCH; j++) {
        if (j + 1 < NCH) loadKV(j + 1, (j + 1) & 1);
        CP_COMMIT();
        CP_WAIT1();
        __syncthreads();
        const int st = j & 1;

        // ---- S = (Qh+Ql) @ Kh^T (2-term, K single fp16) ----
        float accS[8][4];
#pragma unroll
        for (int t = 0; t < 8; t++)
#pragma unroll
            for (int c = 0; c < 4; c++) accS[t][c] = 0.0f;
#pragma unroll
        for (int kk = 0; kk < 8; kk++) {
#pragma unroll
            for (int t = 0; t < 8; t++) {
                uint2 bhv = *(const uint2*)(smc + FKH(st) + (8 * t + qr) * KROWB + kk * 32 + qc * 8);
                uint32_t bH[2] = {bhv.x, bhv.y};
                mma_f16(accS[t], ql[kk], bH);
                mma_f16(accS[t], qh[kk], bH);
            }
        }

        // ---- online softmax (rescale only when max moves) ----
        float mx0 = -INFINITY, mx1 = -INFINITY;
#pragma unroll
        for (int t = 0; t < 8; t++) {
            mx0 = fmaxf(mx0, fmaxf(accS[t][0], accS[t][1]));
            mx1 = fmaxf(mx1, fmaxf(accS[t][2], accS[t][3]));
        }
        mx0 = fmaxf(mx0, __shfl_xor_sync(0xFFFFFFFFu, mx0, 1));
        mx0 = fmaxf(mx0, __shfl_xor_sync(0xFFFFFFFFu, mx0, 2));
        mx1 = fmaxf(mx1, __shfl_xor_sync(0xFFFFFFFFu, mx1, 1));
        mx1 = fmaxf(mx1, __shfl_xor_sync(0xFFFFFFFFu, mx1, 2));
        if (mx0 > mr0 || mx1 > mr1) {
            float mn0 = fmaxf(mr0, mx0), mn1 = fmaxf(mr1, mx1);
            float al0 = __expf(mr0 - mn0), al1 = __expf(mr1 - mn1);
            mr0 = mn0; mr1 = mn1;
            lr0 *= al0; lr1 *= al1;
#pragma unroll
            for (int t = 0; t < 16; t++) {
                accO[t][0] *= al0; accO[t][1] *= al0;
                accO[t][2] *= al1; accO[t][3] *= al1;
            }
        }
        uint32_t ph[8][2];
#pragma unroll
        for (int t = 0; t < 8; t++) {
            float p0 = __expf(accS[t][0] - mr0);
            float p1 = __expf(accS[t][1] - mr0);
            float p2 = __expf(accS[t][2] - mr1);
            float p3 = __expf(accS[t][3] - mr1);
            lr0 += p0 + p1;
            lr1 += p2 + p3;
            ph[t][0] = pack_h2(p0, p1);
            ph[t][1] = pack_h2(p2, p3);
        }

        // ---- O += P @ V (single fp16) ----
#pragma unroll
        for (int kk2 = 0; kk2 < 4; kk2++) {
            uint32_t aH[4] = {ph[2 * kk2][0], ph[2 * kk2][1], ph[2 * kk2 + 1][0], ph[2 * kk2 + 1][1]};
#pragma unroll
            for (int t = 0; t < 16; t++) {
                uint2 vh2 = *(const uint2*)(smc + FV(st) + (8 * t + qr) * VROWB + kk2 * 32 + qc * 8);
                uint32_t bV[2] = {vh2.x, vh2.y};
                mma_f16(accO[t], aH, bV);
            }
        }
        __syncthreads();
    }

    // ---- epilogue: normalize, split, store ----
    lr0 += __shfl_xor_sync(0xFFFFFFFFu, lr0, 1);
    lr0 += __shfl_xor_sync(0xFFFFFFFFu, lr0, 2);
    lr1 += __shfl_xor_sync(0xFFFFFFFFu, lr1, 1);
    lr1 += __shfl_xor_sync(0xFFFFFFFFu, lr1, 2);
    const float i0 = 1.0f / lr0, i1 = 1.0f / lr1;
#pragma unroll
    for (int t = 0; t < 16; t++) {
        int p = 64 * h + 4 * t + qc;
        int pp = (p & ~7) | inv_pair(p & 7);
        uint32_t hh, ll;
        split_h2(make_float2(accO[t][0] * i0, accO[t][1] * i0), hh, ll);
        ((uint32_t*)Chi)[rowA * (DM / 2) + pp] = hh;
        ((uint32_t*)Clo)[rowA * (DM / 2) + pp] = ll;
        split_h2(make_float2(accO[t][2] * i1, accO[t][3] * i1), hh, ll);
        ((uint32_t*)Chi)[(rowA + 8) * (DM / 2) + pp] = hh;
        ((uint32_t*)Clo)[(rowA + 8) * (DM / 2) + pp] = ll;
    }
}

// ---------------- launch -------------------------------------------------------
extern "C" void kernel_launch(void* const* d_in, const int* in_sizes, int n_in,
                              void* d_out, int out_size)
{
    const float* x      = (const float*)d_in[0];
    const float* W_down = (const float*)d_in[1];
    const float* b_down = (const float*)d_in[2];
    const float* W_uk   = (const float*)d_in[3];
    const float* b_uk   = (const float*)d_in[4];
    const float* W_uv   = (const float*)d_in[5];
    const float* b_uv   = (const float*)d_in[6];
    const float* W_q    = (const float*)d_in[7];
    const float* b_q    = (const float*)d_in[8];
    const float* W_o    = (const float*)d_in[9];
    const float* b_o    = (const float*)d_in[10];
    float* out = (float*)d_out;

    void *pa;
    cudaGetSymbolAddress(&pa, g_xhi);   __half* xhi = (__half*)pa;
    cudaGetSymbolAddress(&pa, g_xlo);   __half* xlo = (__half*)pa;
    cudaGetSymbolAddress(&pa, g_lathi); __half* lathi = (__half*)pa;
    cudaGetSymbolAddress(&pa, g_latlo); __half* latlo = (__half*)pa;
    cudaGetSymbolAddress(&pa, g_khi);   __half* khi = (__half*)pa;
    cudaGetSymbolAddress(&pa, g_qhi);   __half* qhi = (__half*)pa;
    cudaGetSymbolAddress(&pa, g_qlo);   __half* qlo = (__half*)pa;
    cudaGetSymbolAddress(&pa, g_ctxhi); __half* ctxhi = (__half*)pa;
    cudaGetSymbolAddress(&pa, g_ctxlo); __half* ctxlo = (__half*)pa;
    cudaGetSymbolAddress(&pa, g_vthi);  __half* vthi = (__half*)pa;
    __half *wdh, *wdl, *wukh, *wukl, *wuvh, *wuvl, *wqh, *wql, *woh, *wol;
    cudaGetSymbolAddress(&pa, g_wdh);  wdh  = (__half*)pa;
    cudaGetSymbolAddress(&pa, g_wdl);  wdl  = (__half*)pa;
    cudaGetSymbolAddress(&pa, g_wukh); wukh = (__half*)pa;
    cudaGetSymbolAddress(&pa, g_wukl); wukl = (__half*)pa;
    cudaGetSymbolAddress(&pa, g_wuvh); wuvh = (__half*)pa;
    cudaGetSymbolAddress(&pa, g_wuvl); wuvl = (__half*)pa;
    cudaGetSymbolAddress(&pa, g_wqh);  wqh  = (__half*)pa;
    cudaGetSymbolAddress(&pa, g_wql);  wql  = (__half*)pa;
    cudaGetSymbolAddress(&pa, g_woh);  woh  = (__half*)pa;
    cudaGetSymbolAddress(&pa, g_wol);  wol  = (__half*)pa;

    static bool attr_set = false;
    if (!attr_set) {
        cudaFuncSetAttribute(hgemm, cudaFuncAttributeMaxDynamicSharedMemorySize, SMEM_HGEMM);
        cudaFuncSetAttribute(flash_kernel, cudaFuncAttributeMaxDynamicSharedMemorySize, SMEM_FLASH);
        attr_set = true;
    }

    const float inv_sqrt_dh = 0.08838834764831845f;
    dim3 blk(256);

    // 0) prep
    prep_kernel<<<dim3(64, 64, 6), dim3(32, 8)>>>(x, W_down, W_uk, W_uv, W_q, W_o);

    // 1) q = (x @ W_q + b_q)/sqrt(DH) -> split Q (hi/lo)
    hgemm<<<dim3(DM/128, MTOT/128), blk, SMEM_HGEMM>>>(
        xhi, xlo, wqh, wql, nullptr, qhi, qlo, nullptr, b_q, DM, DM, DM, DM, inv_sqrt_dh);

    // 2) latents -> split lat (hi/lo)
    hgemm<<<dim3(DL/128, MTOT/128), blk, SMEM_HGEMM>>>(
        xhi, xlo, wdh, wdl, nullptr, lathi, latlo, nullptr, b_down, DM, DM, DM, DL, 1.0f);

    // 3) keys -> K single fp16
    hgemm<<<dim3(DM/128, MTOT/128), blk, SMEM_HGEMM>>>(
        lathi, latlo, wukh, wukl, nullptr, khi, nullptr, nullptr, b_uk, DL, DL, DL, DM, 1.0f);

    // 4) values -> V^T single fp16 (fused transpose)
    hgemm<<<dim3(DM/128, MTOT/128), blk, SMEM_HGEMM>>>(
        lathi, latlo, wuvh, wuvl, nullptr, nullptr, nullptr, vthi, b_uv, DL, DL, DL, DM, 1.0f);

    // 5) flash attention -> split ctx
    flash_kernel<<<dim3(SQ/128, BB*NH), blk, SMEM_FLASH>>>(
        qhi, qlo, khi, vthi, ctxhi, ctxlo);

    // 6) out = ctx @ W_o + b_o
    hgemm<<<dim3(DM/128, MTOT/128), blk, SMEM_HGEMM>>>(
        ctxhi, ctxlo, woh, wol, out, nullptr, nullptr, nullptr, b_o, DM, DM, DM, DM, 1.0f);
}

// round 13
// speedup vs baseline: 1.3576x; 1.0125x over previous
#include <cuda_runtime.h>
#include <cuda_fp16.h>
#include <math.h>
#include <stdint.h>

#define SQ   2048
#define DM   2048
#define DH   128
#define NH   16
#define DL   512
#define BB   4
#define MTOT (BB*SQ)

// ---------------- scratch ------------------------------------------------------
__device__ __half g_xhi[(size_t)MTOT * DM],  g_xlo[(size_t)MTOT * DM];
__device__ __half g_lathi[(size_t)MTOT * DL], g_latlo[(size_t)MTOT * DL];
__device__ __half g_khi[(size_t)MTOT * DM];
__device__ __half g_qhi[(size_t)MTOT * DM];
__device__ __half g_ctxhi[(size_t)MTOT * DM], g_ctxlo[(size_t)MTOT * DM];
__device__ __half g_vthi[(size_t)BB * NH * DH * SQ];
__device__ __half g_wdh[(size_t)DM * DL], g_wdl[(size_t)DM * DL];
__device__ __half g_wukh[(size_t)DL * DM], g_wukl[(size_t)DL * DM];
__device__ __half g_wuvh[(size_t)DL * DM], g_wuvl[(size_t)DL * DM];
__device__ __half g_wqh[(size_t)DM * DM],  g_wql[(size_t)DM * DM];
__device__ __half g_woh[(size_t)DM * DM],  g_wol[(size_t)DM * DM];

// ---------------- helpers ------------------------------------------------------
__device__ __forceinline__ uint32_t smem_u32(const void* p) {
    uint32_t a;
    asm("{ .reg .u64 t; cvta.to.shared.u64 t, %1; cvt.u32.u64 %0, t; }" : "=r"(a) : "l"(p));
    return a;
}
__device__ __forceinline__ void cp_async16(uint32_t dst, const void* src) {
    asm volatile("cp.async.cg.shared.global [%0], [%1], 16;" :: "r"(dst), "l"(src) : "memory");
}
#define CP_COMMIT() asm volatile("cp.async.commit_group;" ::: "memory")
#define CP_WAIT1()  asm volatile("cp.async.wait_group 1;" ::: "memory")

__device__ __forceinline__ void split_h2(float2 f, uint32_t& hi, uint32_t& lo) {
    __half2 h = __float22half2_rn(f);
    float2 back = __half22float2(h);
    __half2 l = __float22half2_rn(make_float2(f.x - back.x, f.y - back.y));
    hi = *(uint32_t*)&h;
    lo = *(uint32_t*)&l;
}
__device__ __forceinline__ uint32_t pack_h2(float a, float b) {
    __half2 h = __float22half2_rn(make_float2(a, b));
    return *(uint32_t*)&h;
}
__device__ __forceinline__ void mma_f16(float* c, const uint32_t* a, const uint32_t* b) {
    asm volatile(
        "mma.sync.aligned.m16n8k16.row.col.f32.f16.f16.f32 "
        "{%0,%1,%2,%3}, {%4,%5,%6,%7}, {%8,%9}, {%0,%1,%2,%3};"
        : "+f"(c[0]), "+f"(c[1]), "+f"(c[2]), "+f"(c[3])
        : "r"(a[0]), "r"(a[1]), "r"(a[2]), "r"(a[3]), "r"(b[0]), "r"(b[1]));
}
__device__ __forceinline__ int inv_pair(int p) { return ((p & 3) << 1) | (p >> 2); }

// ---------------- prep: x split + 5 weight transpose/splits --------------------
__global__ void prep_kernel(const float* __restrict__ x,
                            const float* __restrict__ Wd, const float* __restrict__ Wuk,
                            const float* __restrict__ Wuv, const float* __restrict__ Wq,
                            const float* __restrict__ Wo)
{
    const int z = blockIdx.z;
    if (z == 0) {
        const int tid = threadIdx.y * 32 + threadIdx.x;
        long long base = ((long long)blockIdx.y * 64 + blockIdx.x) * 256 + tid;
        const long long tot = (long long)MTOT * DM / 2;
        for (long long i2 = base; i2 < tot; i2 += (long long)4096 * 256) {
            int d2 = (int)(i2 & (DM / 2 - 1));
            long long row = i2 >> 10;
            int d2p = (d2 & ~7) | inv_pair(d2 & 7);
            float2 v = ((const float2*)x)[i2];
            uint32_t h, l;
            split_h2(v, h, l);
            ((uint32_t*)g_xhi)[row * (DM / 2) + d2p] = h;
            ((uint32_t*)g_xlo)[row * (DM / 2) + d2p] = l;
        }
        return;
    }
    const float* in; __half *hi, *lo; int Cc, R;
    if      (z == 1) { in = Wd;  hi = g_wdh;  lo = g_wdl;  Cc = DL; R = DM; }
    else if (z == 2) { in = Wuk; hi = g_wukh; lo = g_wukl; Cc = DM; R = DL; }
    else if (z == 3) { in = Wuv; hi = g_wuvh; lo = g_wuvl; Cc = DM; R = DL; }
    else if (z == 4) { in = Wq;  hi = g_wqh;  lo = g_wql;  Cc = DM; R = DM; }
    else             { in = Wo;  hi = g_woh;  lo = g_wol;  Cc = DM; R = DM; }
    const int c0 = blockIdx.x * 32, r0 = blockIdx.y * 32;
    if (c0 >= Cc || r0 >= R) return;

    __shared__ float t[32][33];
#pragma unroll
    for (int i = threadIdx.y; i < 32; i += 8)
        t[i][threadIdx.x] = in[(long long)(r0 + i) * Cc + c0 + threadIdx.x];
    __syncthreads();
    const int e = r0 + threadIdx.x;
    const int p = e >> 1, bo = e & 1;
    const int pe = (((p & ~7) | inv_pair(p & 7)) << 1) | bo;
#pragma unroll
    for (int i = threadIdx.y; i < 32; i += 8) {
        float v = t[threadIdx.x][i];
        __half h = __float2half_rn(v);
        __half l = __float2half_rn(v - __half2float(h));
        hi[(long long)(c0 + i) * R + pe] = h;
        lo[(long long)(c0 + i) * R + pe] = l;
    }
}

// ---------------- pre-split fp16 hi/lo GEMM ------------------------------------
#define BK 32
#define AROW 80
#define ARR (128 * AROW)
#define HSTAGE (4 * ARR)
#define SMEM_HGEMM (2 * HSTAGE)         // 81920

__global__ __launch_bounds__(256, 2)
void hgemm(const __half* __restrict__ Ah, const __half* __restrict__ Al,
           const __half* __restrict__ Bh, const __half* __restrict__ Bl,
           float* __restrict__ Cf, __half* __restrict__ Chi, __half* __restrict__ Clo,
           __half* __restrict__ VtHi,
           const float* __restrict__ bias,
           int K, int lda, int ldb, int ldc, float post)
{
    extern __shared__ char sm[];
    const uint32_t smb = smem_u32(sm);
    const int tid = threadIdx.x, wid = tid >> 5, lane = tid & 31;
    const int qr = lane >> 2, qc = lane & 3;
    const int warpM = (wid & 1) * 64, warpN = (wid >> 1) * 32;
    const int m0 = blockIdx.y * 128, n0 = blockIdx.x * 128;

    const __half* A0 = Ah + (long long)m0 * lda;
    const __half* A1 = Al + (long long)m0 * lda;
    const __half* B0 = Bh + (long long)n0 * ldb;
    const __half* B1 = Bl + (long long)n0 * ldb;

    float acc[4][4][4];
#pragma unroll
    for (int mi = 0; mi < 4; mi++)
#pragma unroll
        for (int ni = 0; ni < 4; ni++)
#pragma unroll
            for (int t = 0; t < 4; t++) acc[mi][ni][t] = 0.0f;

    auto load_stage = [&](int t, int s) {
        const int k0 = t * BK;
        uint32_t base = smb + s * HSTAGE;
#pragma unroll
        for (int j = 0; j < 2; j++) {
            int g = tid + j * 256;
            int r = g >> 2, c = g & 3;
            uint32_t off = (uint32_t)(r * AROW + c * 16);
            cp_async16(base + off,           A0 + (long long)r * lda + k0 + c * 8);
            cp_async16(base + ARR + off,     A1 + (long long)r * lda + k0 + c * 8);
            cp_async16(base + 2 * ARR + off, B0 + (long long)r * ldb + k0 + c * 8);
            cp_async16(base + 3 * ARR + off, B1 + (long long)r * ldb + k0 + c * 8);
        }
    };

    const int nk = K / BK;
    load_stage(0, 0); CP_COMMIT();
    load_stage(1, 1); CP_COMMIT();

    for (int i = 0; i < nk; i++) {
        CP_WAIT1();
        __syncthreads();
        const char* s = sm + (i & 1) * HSTAGE;
#pragma unroll
        for (int kk = 0; kk < 2; kk++) {
            uint32_t aH[4][4], aL[4][4], bH[4][2], bL[4][2];
#pragma unroll
            for (int mi = 0; mi < 4; mi++) {
                int row = warpM + mi * 16 + qr;
                uint2 v0 = *(const uint2*)(s + row * AROW + kk * 32 + qc * 8);
                uint2 v1 = *(const uint2*)(s + (row + 8) * AROW + kk * 32 + qc * 8);
                aH[mi][0] = v0.x; aH[mi][2] = v0.y; aH[mi][1] = v1.x; aH[mi][3] = v1.y;
                uint2 w0 = *(const uint2*)(s + ARR + row * AROW + kk * 32 + qc * 8);
                uint2 w1 = *(const uint2*)(s + ARR + (row + 8) * AROW + kk * 32 + qc * 8);
                aL[mi][0] = w0.x; aL[mi][2] = w0.y; aL[mi][1] = w1.x; aL[mi][3] = w1.y;
            }
#pragma unroll
            for (int ni = 0; ni < 4; ni++) {
                int col = warpN + ni * 8 + qr;
                uint2 v = *(const uint2*)(s + 2 * ARR + col * AROW + kk * 32 + qc * 8);
                bH[ni][0] = v.x; bH[ni][1] = v.y;
                uint2 w = *(const uint2*)(s + 3 * ARR + col * AROW + kk * 32 + qc * 8);
                bL[ni][0] = w.x; bL[ni][1] = w.y;
            }
#pragma unroll
            for (int mi = 0; mi < 4; mi++)
#pragma unroll
                for (int ni = 0; ni < 4; ni++) {
                    mma_f16(acc[mi][ni], aL[mi], bH[ni]);
                    mma_f16(acc[mi][ni], aH[mi], bL[ni]);
                    mma_f16(acc[mi][ni], aH[mi], bH[ni]);
                }
        }
        __syncthreads();
        if (i + 2 < nk) load_stage(i + 2, i & 1);
        CP_COMMIT();
    }

    if (VtHi) {
        __syncthreads();
        float* tile = (float*)sm;   // [128][132]
#pragma unroll
        for (int mi = 0; mi < 4; mi++)
#pragma unroll
            for (int ni = 0; ni < 4; ni++) {
                int rl = warpM + mi * 16 + qr;
                int cl = warpN + ni * 8 + qc * 2;
                float2 bv = *(const float2*)(bias + n0 + cl);
                tile[rl * 132 + cl]       = acc[mi][ni][0] + bv.x;
                tile[rl * 132 + cl + 1]   = acc[mi][ni][1] + bv.y;
                tile[(rl + 8) * 132 + cl]     = acc[mi][ni][2] + bv.x;
                tile[(rl + 8) * 132 + cl + 1] = acc[mi][ni][3] + bv.y;
            }
        __syncthreads();
        const int h = n0 >> 7;
        const int bb = m0 >> 11;
        const int s0g = m0 & (SQ - 1);
        const int dl = tid >> 1, sh = (tid & 1) * 64;
        long long base = ((long long)(bb * NH + h) * DH + dl) * SQ + s0g + sh;
#pragma unroll
        for (int pp = 0; pp < 32; pp++) {
            int e = 2 * pp;
            int g = e >> 4, q = pp & 7;
            int off = g * 16 + inv_pair(q) * 2;
            float v0 = tile[(sh + e) * 132 + dl];
            float v1 = tile[(sh + e + 1) * 132 + dl];
            *(uint32_t*)(VtHi + base + off) = pack_h2(v0, v1);
        }
        return;
    }

#pragma unroll
    for (int mi = 0; mi < 4; mi++) {
#pragma unroll
        for (int ni = 0; ni < 4; ni++) {
            int row = m0 + warpM + mi * 16 + qr;
            int colb = n0 + warpN + ni * 8;
            float2 bv = make_float2(0.f, 0.f);
            if (bias) bv = *(const float2*)(bias + colb + qc * 2);
            float2 v0 = make_float2((acc[mi][ni][0] + bv.x) * post, (acc[mi][ni][1] + bv.y) * post);
            float2 v1 = make_float2((acc[mi][ni][2] + bv.x) * post, (acc[mi][ni][3] + bv.y) * post);
            if (Cf) {
                *(float2*)(Cf + (long long)row * ldc + colb + qc * 2) = v0;
                *(float2*)(Cf + (long long)(row + 8) * ldc + colb + qc * 2) = v1;
            }
            if (Chi) {
                int p = (colb >> 1) + qc;
                int pp = (p & ~7) | inv_pair(p & 7);
                uint32_t h, l;
                split_h2(v0, h, l);
                ((uint32_t*)Chi)[(long long)row * (ldc >> 1) + pp] = h;
                if (Clo) ((uint32_t*)Clo)[(long long)row * (ldc >> 1) + pp] = l;
                split_h2(v1, h, l);
                ((uint32_t*)Chi)[(long long)(row + 8) * (ldc >> 1) + pp] = h;
                if (Clo) ((uint32_t*)Clo)[(long long)(row + 8) * (ldc >> 1) + pp] = l;
            }
        }
    }
}

// ---------------- fused flash attention: Q single fp16 in smem, 2 CTAs/SM ------
#define CHUNK 64
#define QROWB 272
#define KROWB 272
#define VROWB 144
#define SM_Q  0
#define KV0   (128 * QROWB)                // 34816
#define KVSTG (64 * KROWB + 128 * VROWB)   // 35840
#define FKH(s) (KV0 + (s) * KVSTG)
#define FV(s)  (KV0 + (s) * KVSTG + 64 * KROWB)
#define SMEM_FLASH (KV0 + 2 * KVSTG)       // 106496 -> 2 CTAs/SM

__global__ __launch_bounds__(256, 2)
void flash_kernel(const __half* __restrict__ Qhi,
                  const __half* __restrict__ Khi, const __half* __restrict__ Vhi,
                  __half* __restrict__ Chi, __half* __restrict__ Clo)
{
    extern __shared__ char smc[];
    const uint32_t smb = smem_u32(smc);
    const int tid = threadIdx.x, wid = tid >> 5, lane = tid & 31;
    const int qr = lane >> 2, qc = lane & 3;
    const int bh = blockIdx.y, b = bh >> 4, h = bh & 15;
    const int q0 = blockIdx.x * 128;

    const long long qbase = (long long)(b * SQ + q0);

    // ---- stage Q (single fp16) into smem once ----
    {
        const __half* qh_g = Qhi + qbase * DM + h * DH;
        for (int g = tid; g < 2048; g += 256) {
            int r = g >> 4, c = g & 15;
            cp_async16(smb + SM_Q + r * QROWB + c * 16, qh_g + (long long)r * DM + c * 8);
        }
    }

    float accO[16][4];
#pragma unroll
    for (int t = 0; t < 16; t++)
#pragma unroll
        for (int c = 0; c < 4; c++) accO[t][c] = 0.0f;
    float mr0 = -INFINITY, mr1 = -INFINITY, lr0 = 0.0f, lr1 = 0.0f;

    const __half* kh_g = Khi + (long long)(b * SQ) * DM + h * DH;
    const __half* vh_g = Vhi + (long long)bh * DH * SQ;

    auto loadKV = [&](int j, int s) {
        int s0 = j * CHUNK;
        for (int g = tid; g < 1024; g += 256) {
            int r = g >> 4, c = g & 15;
            cp_async16(smb + FKH(s) + r * KROWB + c * 16, kh_g + (long long)(s0 + r) * DM + c * 8);
        }
        for (int g = tid; g < 1024; g += 256) {
            int r = g >> 3, c = g & 7;
            cp_async16(smb + FV(s) + r * VROWB + c * 16, vh_g + (long long)r * SQ + s0 + c * 8);
        }
    };

    loadKV(0, 0);        // group 0 = Q + KV0
    CP_COMMIT();

    const char* qhp = smc + SM_Q + (wid * 16 + qr) * QROWB;

    const int NCH = SQ / CHUNK;
    for (int j = 0; j < NCH; j++) {
        if (j + 1 < NCH) loadKV(j + 1, (j + 1) & 1);
        CP_COMMIT();
        CP_WAIT1();               // Q + KV(j) complete; KV(j+1) in flight
        __syncthreads();
        const int st = j & 1;

        // ---- S = Q @ K^T (both single fp16) ----
        float accS[8][4];
#pragma unroll
        for (int t = 0; t < 8; t++)
#pragma unroll
            for (int c = 0; c < 4; c++) accS[t][c] = 0.0f;
#pragma unroll
        for (int kk = 0; kk < 8; kk++) {
            uint32_t aH[4];
            {
                uint2 v0 = *(const uint2*)(qhp + kk * 32 + qc * 8);
                uint2 v1 = *(const uint2*)(qhp + 8 * QROWB + kk * 32 + qc * 8);
                aH[0] = v0.x; aH[2] = v0.y; aH[1] = v1.x; aH[3] = v1.y;
            }
#pragma unroll
            for (int t = 0; t < 8; t++) {
                uint2 bhv = *(const uint2*)(smc + FKH(st) + (8 * t + qr) * KROWB + kk * 32 + qc * 8);
                uint32_t bH[2] = {bhv.x, bhv.y};
                mma_f16(accS[t], aH, bH);
            }
        }

        // ---- online softmax (rescale only when max moves) ----
        float mx0 = -INFINITY, mx1 = -INFINITY;
#pragma unroll
        for (int t = 0; t < 8; t++) {
            mx0 = fmaxf(mx0, fmaxf(accS[t][0], accS[t][1]));
            mx1 = fmaxf(mx1, fmaxf(accS[t][2], accS[t][3]));
        }
        mx0 = fmaxf(mx0, __shfl_xor_sync(0xFFFFFFFFu, mx0, 1));
        mx0 = fmaxf(mx0, __shfl_xor_sync(0xFFFFFFFFu, mx0, 2));
        mx1 = fmaxf(mx1, __shfl_xor_sync(0xFFFFFFFFu, mx1, 1));
        mx1 = fmaxf(mx1, __shfl_xor_sync(0xFFFFFFFFu, mx1, 2));
        if (mx0 > mr0 || mx1 > mr1) {
            float mn0 = fmaxf(mr0, mx0), mn1 = fmaxf(mr1, mx1);
            float al0 = __expf(mr0 - mn0), al1 = __expf(mr1 - mn1);
            mr0 = mn0; mr1 = mn1;
            lr0 *= al0; lr1 *= al1;
#pragma unroll
            for (int t = 0; t < 16; t++) {
                accO[t][0] *= al0; accO[t][1] *= al0;
                accO[t][2] *= al1; accO[t][3] *= al1;
            }
        }
        uint32_t ph[8][2];
#pragma unroll
        for (int t = 0; t < 8; t++) {
            float p0 = __expf(accS[t][0] - mr0);
            float p1 = __expf(accS[t][1] - mr0);
            float p2 = __expf(accS[t][2] - mr1);
            float p3 = __expf(accS[t][3] - mr1);
            lr0 += p0 + p1;
            lr1 += p2 + p3;
            ph[t][0] = pack_h2(p0, p1);
            ph[t][1] = pack_h2(p2, p3);
        }

        // ---- O += P @ V (single fp16) ----
#pragma unroll
        for (int kk2 = 0; kk2 < 4; kk2++) {
            uint32_t aH[4] = {ph[2 * kk2][0], ph[2 * kk2][1], ph[2 * kk2 + 1][0], ph[2 * kk2 + 1][1]};
#pragma unroll
            for (int t = 0; t < 16; t++) {
                uint2 vh2 = *(const uint2*)(smc + FV(st) + (8 * t + qr) * VROWB + kk2 * 32 + qc * 8);
                uint32_t bV[2] = {vh2.x, vh2.y};
                mma_f16(accO[t], aH, bV);
            }
        }
        __syncthreads();
    }

    // ---- epilogue: normalize, split, store ----
    lr0 += __shfl_xor_sync(0xFFFFFFFFu, lr0, 1);
    lr0 += __shfl_xor_sync(0xFFFFFFFFu, lr0, 2);
    lr1 += __shfl_xor_sync(0xFFFFFFFFu, lr1, 1);
    lr1 += __shfl_xor_sync(0xFFFFFFFFu, lr1, 2);
    const float i0 = 1.0f / lr0, i1 = 1.0f / lr1;
    const long long rowA = qbase + wid * 16 + qr;
#pragma unroll
    for (int t = 0; t < 16; t++) {
        int p = 64 * h + 4 * t + qc;
        int pp = (p & ~7) | inv_pair(p & 7);
        uint32_t hh, ll;
        split_h2(make_float2(accO[t][0] * i0, accO[t][1] * i0), hh, ll);
        ((uint32_t*)Chi)[rowA * (DM / 2) + pp] = hh;
        ((uint32_t*)Clo)[rowA * (DM / 2) + pp] = ll;
        split_h2(make_float2(accO[t][2] * i1, accO[t][3] * i1), hh, ll);
        ((uint32_t*)Chi)[(rowA + 8) * (DM / 2) + pp] = hh;
        ((uint32_t*)Clo)[(rowA + 8) * (DM / 2) + pp] = ll;
    }
}

// ---------------- launch -------------------------------------------------------
extern "C" void kernel_launch(void* const* d_in, const int* in_sizes, int n_in,
                              void* d_out, int out_size)
{
    const float* x      = (const float*)d_in[0];
    const float* W_down = (const float*)d_in[1];
    const float* b_down = (const float*)d_in[2];
    const float* W_uk   = (const float*)d_in[3];
    const float* b_uk   = (const float*)d_in[4];
    const float* W_uv   = (const float*)d_in[5];
    const float* b_uv   = (const float*)d_in[6];
    const float* W_q    = (const float*)d_in[7];
    const float* b_q    = (const float*)d_in[8];
    const float* W_o    = (const float*)d_in[9];
    const float* b_o    = (const float*)d_in[10];
    float* out = (float*)d_out;

    void *pa;
    cudaGetSymbolAddress(&pa, g_xhi);   __half* xhi = (__half*)pa;
    cudaGetSymbolAddress(&pa, g_xlo);   __half* xlo = (__half*)pa;
    cudaGetSymbolAddress(&pa, g_lathi); __half* lathi = (__half*)pa;
    cudaGetSymbolAddress(&pa, g_latlo); __half* latlo = (__half*)pa;
    cudaGetSymbolAddress(&pa, g_khi);   __half* khi = (__half*)pa;
    cudaGetSymbolAddress(&pa, g_qhi);   __half* qhi = (__half*)pa;
    cudaGetSymbolAddress(&pa, g_ctxhi); __half* ctxhi = (__half*)pa;
    cudaGetSymbolAddress(&pa, g_ctxlo); __half* ctxlo = (__half*)pa;
    cudaGetSymbolAddress(&pa, g_vthi);  __half* vthi = (__half*)pa;
    __half *wdh, *wdl, *wukh, *wukl, *wuvh, *wuvl, *wqh, *wql, *woh, *wol;
    cudaGetSymbolAddress(&pa, g_wdh);  wdh  = (__half*)pa;
    cudaGetSymbolAddress(&pa, g_wdl);  wdl  = (__half*)pa;
    cudaGetSymbolAddress(&pa, g_wukh); wukh = (__half*)pa;
    cudaGetSymbolAddress(&pa, g_wukl); wukl = (__half*)pa;
    cudaGetSymbolAddress(&pa, g_wuvh); wuvh = (__half*)pa;
    cudaGetSymbolAddress(&pa, g_wuvl); wuvl = (__half*)pa;
    cudaGetSymbolAddress(&pa, g_wqh);  wqh  = (__half*)pa;
    cudaGetSymbolAddress(&pa, g_wql);  wql  = (__half*)pa;
    cudaGetSymbolAddress(&pa, g_woh);  woh  = (__half*)pa;
    cudaGetSymbolAddress(&pa, g_wol);  wol  = (__half*)pa;

    static bool attr_set = false;
    if (!attr_set) {
        cudaFuncSetAttribute(hgemm, cudaFuncAttributeMaxDynamicSharedMemorySize, SMEM_HGEMM);
        cudaFuncSetAttribute(flash_kernel, cudaFuncAttributeMaxDynamicSharedMemorySize, SMEM_FLASH);
        attr_set = true;
    }

    const float inv_sqrt_dh = 0.08838834764831845f;
    dim3 blk(256);

    // 0) prep
    prep_kernel<<<dim3(64, 64, 6), dim3(32, 8)>>>(x, W_down, W_uk, W_uv, W_q, W_o);

    // 1) q = (x @ W_q + b_q)/sqrt(DH) -> Q single fp16
    hgemm<<<dim3(DM/128, MTOT/128), blk, SMEM_HGEMM>>>(
        xhi, xlo, wqh, wql, nullptr, qhi, nullptr, nullptr, b_q, DM, DM, DM, DM, inv_sqrt_dh);

    // 2) latents -> split lat (hi/lo)
    hgemm<<<dim3(DL/128, MTOT/128), blk, SMEM_HGEMM>>>(
        xhi, xlo, wdh, wdl, nullptr, lathi, latlo, nullptr, b_down, DM, DM, DM, DL, 1.0f);

    // 3) keys -> K single fp16
    hgemm<<<dim3(DM/128, MTOT/128), blk, SMEM_HGEMM>>>(
        lathi, latlo, wukh, wukl, nullptr, khi, nullptr, nullptr, b_uk, DL, DL, DL, DM, 1.0f);

    // 4) values -> V^T single fp16 (fused transpose)
    hgemm<<<dim3(DM/128, MTOT/128), blk, SMEM_HGEMM>>>(
        lathi, latlo, wuvh, wuvl, nullptr, nullptr, nullptr, vthi, b_uv, DL, DL, DL, DM, 1.0f);

    // 5) flash attention (2 CTAs/SM) -> split ctx
    flash_kernel<<<dim3(SQ/128, BB*NH), blk, SMEM_FLASH>>>(
        qhi, khi, vthi, ctxhi, ctxlo);

    // 6) out = ctx @ W_o + b_o
    hgemm<<<dim3(DM/128, MTOT/128), blk, SMEM_HGEMM>>>(
        ctxhi, ctxlo, woh, wol, out, nullptr, nullptr, nullptr, b_o, DM, DM, DM, DM, 1.0f);
}

// round 14
// speedup vs baseline: 1.3753x; 1.0131x over previous
#include <cuda_runtime.h>
#include <cuda_fp16.h>
#include <math.h>
#include <stdint.h>

#define SQ   2048
#define DM   2048
#define DH   128
#define NH   16
#define DL   512
#define BB   4
#define MTOT (BB*SQ)

// ---------------- scratch ------------------------------------------------------
__device__ __half g_xhi[(size_t)MTOT * DM],  g_xlo[(size_t)MTOT * DM];
__device__ __half g_lathi[(size_t)MTOT * DL], g_latlo[(size_t)MTOT * DL];
__device__ __half g_khi[(size_t)MTOT * DM];
__device__ __half g_qhi[(size_t)MTOT * DM];
__device__ __half g_ctxhi[(size_t)MTOT * DM], g_ctxlo[(size_t)MTOT * DM];
__device__ __half g_vthi[(size_t)BB * NH * DH * SQ];
__device__ __half g_wdh[(size_t)DM * DL], g_wdl[(size_t)DM * DL];
__device__ __half g_wukh[(size_t)DL * DM], g_wukl[(size_t)DL * DM];
__device__ __half g_wuvh[(size_t)DL * DM], g_wuvl[(size_t)DL * DM];
__device__ __half g_wqh[(size_t)DM * DM],  g_wql[(size_t)DM * DM];
__device__ __half g_woh[(size_t)DM * DM],  g_wol[(size_t)DM * DM];

// ---------------- helpers ------------------------------------------------------
__device__ __forceinline__ uint32_t smem_u32(const void* p) {
    uint32_t a;
    asm("{ .reg .u64 t; cvta.to.shared.u64 t, %1; cvt.u32.u64 %0, t; }" : "=r"(a) : "l"(p));
    return a;
}
__device__ __forceinline__ void cp_async16(uint32_t dst, const void* src) {
    asm volatile("cp.async.cg.shared.global [%0], [%1], 16;" :: "r"(dst), "l"(src) : "memory");
}
#define CP_COMMIT() asm volatile("cp.async.commit_group;" ::: "memory")
#define CP_WAIT1()  asm volatile("cp.async.wait_group 1;" ::: "memory")

__device__ __forceinline__ void split_h2(float2 f, uint32_t& hi, uint32_t& lo) {
    __half2 h = __float22half2_rn(f);
    float2 back = __half22float2(h);
    __half2 l = __float22half2_rn(make_float2(f.x - back.x, f.y - back.y));
    hi = *(uint32_t*)&h;
    lo = *(uint32_t*)&l;
}
__device__ __forceinline__ uint32_t pack_h2(float a, float b) {
    __half2 h = __float22half2_rn(make_float2(a, b));
    return *(uint32_t*)&h;
}
__device__ __forceinline__ void mma_f16(float* c, const uint32_t* a, const uint32_t* b) {
    asm volatile(
        "mma.sync.aligned.m16n8k16.row.col.f32.f16.f16.f32 "
        "{%0,%1,%2,%3}, {%4,%5,%6,%7}, {%8,%9}, {%0,%1,%2,%3};"
        : "+f"(c[0]), "+f"(c[1]), "+f"(c[2]), "+f"(c[3])
        : "r"(a[0]), "r"(a[1]), "r"(a[2]), "r"(a[3]), "r"(b[0]), "r"(b[1]));
}
__device__ __forceinline__ int inv_pair(int p) { return ((p & 3) << 1) | (p >> 2); }

// ---------------- prep: x split + 5 weight transpose/splits --------------------
__global__ void prep_kernel(const float* __restrict__ x,
                            const float* __restrict__ Wd, const float* __restrict__ Wuk,
                            const float* __restrict__ Wuv, const float* __restrict__ Wq,
                            const float* __restrict__ Wo)
{
    const int z = blockIdx.z;
    if (z == 0) {
        const int tid = threadIdx.y * 32 + threadIdx.x;
        long long base = ((long long)blockIdx.y * 64 + blockIdx.x) * 256 + tid;
        const long long tot = (long long)MTOT * DM / 2;
        for (long long i2 = base; i2 < tot; i2 += (long long)4096 * 256) {
            int d2 = (int)(i2 & (DM / 2 - 1));
            long long row = i2 >> 10;
            int d2p = (d2 & ~7) | inv_pair(d2 & 7);
            float2 v = ((const float2*)x)[i2];
            uint32_t h, l;
            split_h2(v, h, l);
            ((uint32_t*)g_xhi)[row * (DM / 2) + d2p] = h;
            ((uint32_t*)g_xlo)[row * (DM / 2) + d2p] = l;
        }
        return;
    }
    const float* in; __half *hi, *lo; int Cc, R;
    if      (z == 1) { in = Wd;  hi = g_wdh;  lo = g_wdl;  Cc = DL; R = DM; }
    else if (z == 2) { in = Wuk; hi = g_wukh; lo = g_wukl; Cc = DM; R = DL; }
    else if (z == 3) { in = Wuv; hi = g_wuvh; lo = g_wuvl; Cc = DM; R = DL; }
    else if (z == 4) { in = Wq;  hi = g_wqh;  lo = g_wql;  Cc = DM; R = DM; }
    else             { in = Wo;  hi = g_woh;  lo = g_wol;  Cc = DM; R = DM; }
    const int c0 = blockIdx.x * 32, r0 = blockIdx.y * 32;
    if (c0 >= Cc || r0 >= R) return;

    __shared__ float t[32][33];
#pragma unroll
    for (int i = threadIdx.y; i < 32; i += 8)
        t[i][threadIdx.x] = in[(long long)(r0 + i) * Cc + c0 + threadIdx.x];
    __syncthreads();
    const int e = r0 + threadIdx.x;
    const int p = e >> 1, bo = e & 1;
    const int pe = (((p & ~7) | inv_pair(p & 7)) << 1) | bo;
#pragma unroll
    for (int i = threadIdx.y; i < 32; i += 8) {
        float v = t[threadIdx.x][i];
        __half h = __float2half_rn(v);
        __half l = __float2half_rn(v - __half2float(h));
        hi[(long long)(c0 + i) * R + pe] = h;
        lo[(long long)(c0 + i) * R + pe] = l;
    }
}

// ---------------- pre-split fp16 hi/lo GEMM ------------------------------------
#define BK 32
#define AROW 80
#define ARR (128 * AROW)
#define HSTAGE (4 * ARR)
#define SMEM_HGEMM (2 * HSTAGE)         // 81920

__global__ __launch_bounds__(256, 2)
void hgemm(const __half* __restrict__ Ah, const __half* __restrict__ Al,
           const __half* __restrict__ Bh, const __half* __restrict__ Bl,
           float* __restrict__ Cf, __half* __restrict__ Chi, __half* __restrict__ Clo,
           __half* __restrict__ VtHi,
           const float* __restrict__ bias,
           int K, int lda, int ldb, int ldc, float post)
{
    extern __shared__ char sm[];
    const uint32_t smb = smem_u32(sm);
    const int tid = threadIdx.x, wid = tid >> 5, lane = tid & 31;
    const int qr = lane >> 2, qc = lane & 3;
    const int warpM = (wid & 1) * 64, warpN = (wid >> 1) * 32;
    const int m0 = blockIdx.y * 128, n0 = blockIdx.x * 128;

    const __half* A0 = Ah + (long long)m0 * lda;
    const __half* A1 = Al + (long long)m0 * lda;
    const __half* B0 = Bh + (long long)n0 * ldb;
    const __half* B1 = Bl + (long long)n0 * ldb;

    float acc[4][4][4];
#pragma unroll
    for (int mi = 0; mi < 4; mi++)
#pragma unroll
        for (int ni = 0; ni < 4; ni++)
#pragma unroll
            for (int t = 0; t < 4; t++) acc[mi][ni][t] = 0.0f;

    auto load_stage = [&](int t, int s) {
        const int k0 = t * BK;
        uint32_t base = smb + s * HSTAGE;
#pragma unroll
        for (int j = 0; j < 2; j++) {
            int g = tid + j * 256;
            int r = g >> 2, c = g & 3;
            uint32_t off = (uint32_t)(r * AROW + c * 16);
            cp_async16(base + off,           A0 + (long long)r * lda + k0 + c * 8);
            cp_async16(base + ARR + off,     A1 + (long long)r * lda + k0 + c * 8);
            cp_async16(base + 2 * ARR + off, B0 + (long long)r * ldb + k0 + c * 8);
            cp_async16(base + 3 * ARR + off, B1 + (long long)r * ldb + k0 + c * 8);
        }
    };

    const int nk = K / BK;
    load_stage(0, 0); CP_COMMIT();
    load_stage(1, 1); CP_COMMIT();

    for (int i = 0; i < nk; i++) {
        CP_WAIT1();
        __syncthreads();
        const char* s = sm + (i & 1) * HSTAGE;
#pragma unroll
        for (int kk = 0; kk < 2; kk++) {
            uint32_t aH[4][4], aL[4][4], bH[4][2], bL[4][2];
#pragma unroll
            for (int mi = 0; mi < 4; mi++) {
                int row = warpM + mi * 16 + qr;
                uint2 v0 = *(const uint2*)(s + row * AROW + kk * 32 + qc * 8);
                uint2 v1 = *(const uint2*)(s + (row + 8) * AROW + kk * 32 + qc * 8);
                aH[mi][0] = v0.x; aH[mi][2] = v0.y; aH[mi][1] = v1.x; aH[mi][3] = v1.y;
                uint2 w0 = *(const uint2*)(s + ARR + row * AROW + kk * 32 + qc * 8);
                uint2 w1 = *(const uint2*)(s + ARR + (row + 8) * AROW + kk * 32 + qc * 8);
                aL[mi][0] = w0.x; aL[mi][2] = w0.y; aL[mi][1] = w1.x; aL[mi][3] = w1.y;
            }
#pragma unroll
            for (int ni = 0; ni < 4; ni++) {
                int col = warpN + ni * 8 + qr;
                uint2 v = *(const uint2*)(s + 2 * ARR + col * AROW + kk * 32 + qc * 8);
                bH[ni][0] = v.x; bH[ni][1] = v.y;
                uint2 w = *(const uint2*)(s + 3 * ARR + col * AROW + kk * 32 + qc * 8);
                bL[ni][0] = w.x; bL[ni][1] = w.y;
            }
#pragma unroll
            for (int mi = 0; mi < 4; mi++)
#pragma unroll
                for (int ni = 0; ni < 4; ni++) {
                    mma_f16(acc[mi][ni], aL[mi], bH[ni]);
                    mma_f16(acc[mi][ni], aH[mi], bL[ni]);
                    mma_f16(acc[mi][ni], aH[mi], bH[ni]);
                }
        }
        __syncthreads();
        if (i + 2 < nk) load_stage(i + 2, i & 1);
        CP_COMMIT();
    }

    if (VtHi) {
        // V^T epilogue, coalesced: stage fp32 tile, each thread emits 32B-contig
        // permuted groups along s (uint4 stores).
        __syncthreads();
        float* tile = (float*)sm;   // [128 s][132 d]
#pragma unroll
        for (int mi = 0; mi < 4; mi++)
#pragma unroll
            for (int ni = 0; ni < 4; ni++) {
                int rl = warpM + mi * 16 + qr;
                int cl = warpN + ni * 8 + qc * 2;
                float2 bv = *(const float2*)(bias + n0 + cl);
                tile[rl * 132 + cl]       = acc[mi][ni][0] + bv.x;
                tile[rl * 132 + cl + 1]   = acc[mi][ni][1] + bv.y;
                tile[(rl + 8) * 132 + cl]     = acc[mi][ni][2] + bv.x;
                tile[(rl + 8) * 132 + cl + 1] = acc[mi][ni][3] + bv.y;
            }
        __syncthreads();
        const int h = n0 >> 7;
        const int bb = m0 >> 11;
        const int s0g = m0 & (SQ - 1);
        const int dl = tid & 127;          // d-row
        const int sh = (tid >> 7) * 64;    // s-half (0 or 64)
        __half* orow = VtHi + ((long long)(bb * NH + h) * DH + dl) * SQ + s0g + sh;
#pragma unroll
        for (int g = 0; g < 4; g++) {      // 4 groups of 16 s
            __half outh[16];
#pragma unroll
            for (int q = 0; q < 8; q++) {
                int sl = sh + g * 16 + 2 * q;
                int d = inv_pair(q) * 2;
                outh[d]     = __float2half_rn(tile[sl * 132 + dl]);
                outh[d + 1] = __float2half_rn(tile[(sl + 1) * 132 + dl]);
            }
            *(uint4*)(orow + g * 16)     = *(uint4*)&outh[0];
            *(uint4*)(orow + g * 16 + 8) = *(uint4*)&outh[8];
        }
        return;
    }

#pragma unroll
    for (int mi = 0; mi < 4; mi++) {
#pragma unroll
        for (int ni = 0; ni < 4; ni++) {
            int row = m0 + warpM + mi * 16 + qr;
            int colb = n0 + warpN + ni * 8;
            float2 bv = make_float2(0.f, 0.f);
            if (bias) bv = *(const float2*)(bias + colb + qc * 2);
            float2 v0 = make_float2((acc[mi][ni][0] + bv.x) * post, (acc[mi][ni][1] + bv.y) * post);
            float2 v1 = make_float2((acc[mi][ni][2] + bv.x) * post, (acc[mi][ni][3] + bv.y) * post);
            if (Cf) {
                *(float2*)(Cf + (long long)row * ldc + colb + qc * 2) = v0;
                *(float2*)(Cf + (long long)(row + 8) * ldc + colb + qc * 2) = v1;
            }
            if (Chi) {
                int p = (colb >> 1) + qc;
                int pp = (p & ~7) | inv_pair(p & 7);
                uint32_t h, l;
                split_h2(v0, h, l);
                ((uint32_t*)Chi)[(long long)row * (ldc >> 1) + pp] = h;
                if (Clo) ((uint32_t*)Clo)[(long long)row * (ldc >> 1) + pp] = l;
                split_h2(v1, h, l);
                ((uint32_t*)Chi)[(long long)(row + 8) * (ldc >> 1) + pp] = h;
                if (Clo) ((uint32_t*)Clo)[(long long)(row + 8) * (ldc >> 1) + pp] = l;
            }
        }
    }
}

// ---------------- fused flash attention: CHUNK=128, 16 chunks ------------------
#define CHUNK 128
#define QROWB 272
#define KROWB 272
#define VROWB 272
#define SM_Q  0
#define KV0   (128 * QROWB)                // 34816
#define KVSTG (128 * KROWB + 128 * VROWB)  // 69632
#define FKH(s) (KV0 + (s) * KVSTG)
#define FV(s)  (KV0 + (s) * KVSTG + 128 * KROWB)
#define SMEM_FLASH (KV0 + 2 * KVSTG)       // 174080

__global__ __launch_bounds__(256, 1)
void flash_kernel(const __half* __restrict__ Qhi,
                  const __half* __restrict__ Khi, const __half* __restrict__ Vhi,
                  __half* __restrict__ Chi, __half* __restrict__ Clo)
{
    extern __shared__ char smc[];
    const uint32_t smb = smem_u32(smc);
    const int tid = threadIdx.x, wid = tid >> 5, lane = tid & 31;
    const int qr = lane >> 2, qc = lane & 3;
    const int bh = blockIdx.y, b = bh >> 4, h = bh & 15;
    const int q0 = blockIdx.x * 128;

    const long long qbase = (long long)(b * SQ + q0);

    // ---- stage Q (single fp16) into smem once ----
    {
        const __half* qh_g = Qhi + qbase * DM + h * DH;
        for (int g = tid; g < 2048; g += 256) {
            int r = g >> 4, c = g & 15;
            cp_async16(smb + SM_Q + r * QROWB + c * 16, qh_g + (long long)r * DM + c * 8);
        }
    }

    float accO[16][4];
#pragma unroll
    for (int t = 0; t < 16; t++)
#pragma unroll
        for (int c = 0; c < 4; c++) accO[t][c] = 0.0f;
    float mr0 = -INFINITY, mr1 = -INFINITY, lr0 = 0.0f, lr1 = 0.0f;

    const __half* kh_g = Khi + (long long)(b * SQ) * DM + h * DH;
    const __half* vh_g = Vhi + (long long)bh * DH * SQ;

    auto loadKV = [&](int j, int s) {
        int s0 = j * CHUNK;
        for (int g = tid; g < 2048; g += 256) {
            int r = g >> 4, c = g & 15;
            cp_async16(smb + FKH(s) + r * KROWB + c * 16, kh_g + (long long)(s0 + r) * DM + c * 8);
        }
        for (int g = tid; g < 2048; g += 256) {
            int r = g >> 4, c = g & 15;
            cp_async16(smb + FV(s) + r * VROWB + c * 16, vh_g + (long long)r * SQ + s0 + c * 8);
        }
    };

    loadKV(0, 0);        // group 0 = Q + KV0
    CP_COMMIT();

    const char* qhp = smc + SM_Q + (wid * 16 + qr) * QROWB;

    const int NCH = SQ / CHUNK;   // 16
    for (int j = 0; j < NCH; j++) {
        if (j + 1 < NCH) loadKV(j + 1, (j + 1) & 1);
        CP_COMMIT();
        CP_WAIT1();               // Q + KV(j) complete; KV(j+1) in flight
        __syncthreads();
        const int st = j & 1;

        // ---- S = Q @ K^T (128 keys = 16 n8-tiles) ----
        float accS[16][4];
#pragma unroll
        for (int t = 0; t < 16; t++)
#pragma unroll
            for (int c = 0; c < 4; c++) accS[t][c] = 0.0f;
#pragma unroll
        for (int kk = 0; kk < 8; kk++) {
            uint32_t aH[4];
            {
                uint2 v0 = *(const uint2*)(qhp + kk * 32 + qc * 8);
                uint2 v1 = *(const uint2*)(qhp + 8 * QROWB + kk * 32 + qc * 8);
                aH[0] = v0.x; aH[2] = v0.y; aH[1] = v1.x; aH[3] = v1.y;
            }
#pragma unroll
            for (int t = 0; t < 16; t++) {
                uint2 bhv = *(const uint2*)(smc + FKH(st) + (8 * t + qr) * KROWB + kk * 32 + qc * 8);
                uint32_t bH[2] = {bhv.x, bhv.y};
                mma_f16(accS[t], aH, bH);
            }
        }

        // ---- online softmax max update ----
        float mx0 = -INFINITY, mx1 = -INFINITY;
#pragma unroll
        for (int t = 0; t < 16; t++) {
            mx0 = fmaxf(mx0, fmaxf(accS[t][0], accS[t][1]));
            mx1 = fmaxf(mx1, fmaxf(accS[t][2], accS[t][3]));
        }
        mx0 = fmaxf(mx0, __shfl_xor_sync(0xFFFFFFFFu, mx0, 1));
        mx0 = fmaxf(mx0, __shfl_xor_sync(0xFFFFFFFFu, mx0, 2));
        mx1 = fmaxf(mx1, __shfl_xor_sync(0xFFFFFFFFu, mx1, 1));
        mx1 = fmaxf(mx1, __shfl_xor_sync(0xFFFFFFFFu, mx1, 2));
        if (mx0 > mr0 || mx1 > mr1) {
            float mn0 = fmaxf(mr0, mx0), mn1 = fmaxf(mr1, mx1);
            float al0 = __expf(mr0 - mn0), al1 = __expf(mr1 - mn1);
            mr0 = mn0; mr1 = mn1;
            lr0 *= al0; lr1 *= al1;
#pragma unroll
            for (int t = 0; t < 16; t++) {
                accO[t][0] *= al0; accO[t][1] *= al0;
                accO[t][2] *= al1; accO[t][3] *= al1;
            }
        }

        // ---- exp + PV in two t-halves (caps live registers) ----
#pragma unroll
        for (int h2 = 0; h2 < 2; h2++) {
            uint32_t ph[8][2];
#pragma unroll
            for (int u = 0; u < 8; u++) {
                int t = 8 * h2 + u;
                float p0 = __expf(accS[t][0] - mr0);
                float p1 = __expf(accS[t][1] - mr0);
                float p2 = __expf(accS[t][2] - mr1);
                float p3 = __expf(accS[t][3] - mr1);
                lr0 += p0 + p1;
                lr1 += p2 + p3;
                ph[u][0] = pack_h2(p0, p1);
                ph[u][1] = pack_h2(p2, p3);
            }
#pragma unroll
            for (int kk2 = 0; kk2 < 4; kk2++) {
                uint32_t aH[4] = {ph[2 * kk2][0], ph[2 * kk2][1],
                                  ph[2 * kk2 + 1][0], ph[2 * kk2 + 1][1]};
                int kko = (4 * h2 + kk2) * 32;   // key offset within chunk (bytes/2... pairs)
#pragma unroll
                for (int t = 0; t < 16; t++) {
                    uint2 vh2 = *(const uint2*)(smc + FV(st) + (8 * t + qr) * VROWB + kko + qc * 8);
                    uint32_t bV[2] = {vh2.x, vh2.y};
                    mma_f16(accO[t], aH, bV);
                }
            }
        }
        __syncthreads();
    }

    // ---- epilogue: normalize, split, store ----
    lr0 += __shfl_xor_sync(0xFFFFFFFFu, lr0, 1);
    lr0 += __shfl_xor_sync(0xFFFFFFFFu, lr0, 2);
    lr1 += __shfl_xor_sync(0xFFFFFFFFu, lr1, 1);
    lr1 += __shfl_xor_sync(0xFFFFFFFFu, lr1, 2);
    const float i0 = 1.0f / lr0, i1 = 1.0f / lr1;
    const long long rowA = qbase + wid * 16 + qr;
#pragma unroll
    for (int t = 0; t < 16; t++) {
        int p = 64 * h + 4 * t + qc;
        int pp = (p & ~7) | inv_pair(p & 7);
        uint32_t hh, ll;
        split_h2(make_float2(accO[t][0] * i0, accO[t][1] * i0), hh, ll);
        ((uint32_t*)Chi)[rowA * (DM / 2) + pp] = hh;
        ((uint32_t*)Clo)[rowA * (DM / 2) + pp] = ll;
        split_h2(make_float2(accO[t][2] * i1, accO[t][3] * i1), hh, ll);
        ((uint32_t*)Chi)[(rowA + 8) * (DM / 2) + pp] = hh;
        ((uint32_t*)Clo)[(rowA + 8) * (DM / 2) + pp] = ll;
    }
}

// ---------------- launch -------------------------------------------------------
extern "C" void kernel_launch(void* const* d_in, const int* in_sizes, int n_in,
                              void* d_out, int out_size)
{
    const float* x      = (const float*)d_in[0];
    const float* W_down = (const float*)d_in[1];
    const float* b_down = (const float*)d_in[2];
    const float* W_uk   = (const float*)d_in[3];
    const float* b_uk   = (const float*)d_in[4];
    const float* W_uv   = (const float*)d_in[5];
    const float* b_uv   = (const float*)d_in[6];
    const float* W_q    = (const float*)d_in[7];
    const float* b_q    = (const float*)d_in[8];
    const float* W_o    = (const float*)d_in[9];
    const float* b_o    = (const float*)d_in[10];
    float* out = (float*)d_out;

    void *pa;
    cudaGetSymbolAddress(&pa, g_xhi);   __half* xhi = (__half*)pa;
    cudaGetSymbolAddress(&pa, g_xlo);   __half* xlo = (__half*)pa;
    cudaGetSymbolAddress(&pa, g_lathi); __half* lathi = (__half*)pa;
    cudaGetSymbolAddress(&pa, g_latlo); __half* latlo = (__half*)pa;
    cudaGetSymbolAddress(&pa, g_khi);   __half* khi = (__half*)pa;
    cudaGetSymbolAddress(&pa, g_qhi);   __half* qhi = (__half*)pa;
    cudaGetSymbolAddress(&pa, g_ctxhi); __half* ctxhi = (__half*)pa;
    cudaGetSymbolAddress(&pa, g_ctxlo); __half* ctxlo = (__half*)pa;
    cudaGetSymbolAddress(&pa, g_vthi);  __half* vthi = (__half*)pa;
    __half *wdh, *wdl, *wukh, *wukl, *wuvh, *wuvl, *wqh, *wql, *woh, *wol;
    cudaGetSymbolAddress(&pa, g_wdh);  wdh  = (__half*)pa;
    cudaGetSymbolAddress(&pa, g_wdl);  wdl  = (__half*)pa;
    cudaGetSymbolAddress(&pa, g_wukh); wukh = (__half*)pa;
    cudaGetSymbolAddress(&pa, g_wukl); wukl = (__half*)pa;
    cudaGetSymbolAddress(&pa, g_wuvh); wuvh = (__half*)pa;
    cudaGetSymbolAddress(&pa, g_wuvl); wuvl = (__half*)pa;
    cudaGetSymbolAddress(&pa, g_wqh);  wqh  = (__half*)pa;
    cudaGetSymbolAddress(&pa, g_wql);  wql  = (__half*)pa;
    cudaGetSymbolAddress(&pa, g_woh);  woh  = (__half*)pa;
    cudaGetSymbolAddress(&pa, g_wol);  wol  = (__half*)pa;

    static bool attr_set = false;
    if (!attr_set) {
        cudaFuncSetAttribute(hgemm, cudaFuncAttributeMaxDynamicSharedMemorySize, SMEM_HGEMM);
        cudaFuncSetAttribute(flash_kernel, cudaFuncAttributeMaxDynamicSharedMemorySize, SMEM_FLASH);
        attr_set = true;
    }

    const float inv_sqrt_dh = 0.08838834764831845f;
    dim3 blk(256);

    // 0) prep
    prep_kernel<<<dim3(64, 64, 6), dim3(32, 8)>>>(x, W_down, W_uk, W_uv, W_q, W_o);

    // 1) q = (x @ W_q + b_q)/sqrt(DH) -> Q single fp16
    hgemm<<<dim3(DM/128, MTOT/128), blk, SMEM_HGEMM>>>(
        xhi, xlo, wqh, wql, nullptr, qhi, nullptr, nullptr, b_q, DM, DM, DM, DM, inv_sqrt_dh);

    // 2) latents -> split lat (hi/lo)
    hgemm<<<dim3(DL/128, MTOT/128), blk, SMEM_HGEMM>>>(
        xhi, xlo, wdh, wdl, nullptr, lathi, latlo, nullptr, b_down, DM, DM, DM, DL, 1.0f);

    // 3) keys -> K single fp16
    hgemm<<<dim3(DM/128, MTOT/128), blk, SMEM_HGEMM>>>(
        lathi, latlo, wukh, wukl, nullptr, khi, nullptr, nullptr, b_uk, DL, DL, DL, DM, 1.0f);

    // 4) values -> V^T single fp16 (fused transpose, coalesced epilogue)
    hgemm<<<dim3(DM/128, MTOT/128), blk, SMEM_HGEMM>>>(
        lathi, latlo, wuvh, wuvl, nullptr, nullptr, nullptr, vthi, b_uv, DL, DL, DL, DM, 1.0f);

    // 5) flash attention (CHUNK=128, 16 chunks) -> split ctx
    flash_kernel<<<dim3(SQ/128, BB*NH), blk, SMEM_FLASH>>>(
        qhi, khi, vthi, ctxhi, ctxlo);

    // 6) out = ctx @ W_o + b_o
    hgemm<<<dim3(DM/128, MTOT/128), blk, SMEM_HGEMM>>>(
        ctxhi, ctxlo, woh, wol, out, nullptr, nullptr, nullptr, b_o, DM, DM, DM, DM, 1.0f);
}

// round 16
// speedup vs baseline: 1.7390x; 1.2644x over previous
#include <cuda_runtime.h>
#include <cuda_fp16.h>
#include <math.h>
#include <stdint.h>

#define SQ   2048
#define DM   2048
#define DH   128
#define NH   16
#define DL   512
#define BB   4
#define MTOT (BB*SQ)

// ---------------- scratch ------------------------------------------------------
__device__ __half g_xh[(size_t)MTOT * DM];
__device__ __half g_lath[(size_t)MTOT * DL];
__device__ __half g_kh[(size_t)MTOT * DM];
__device__ __half g_qh[(size_t)MTOT * DM];
__device__ __half g_ctxh[(size_t)MTOT * DM];
__device__ __half g_vth[(size_t)BB * NH * DH * SQ];
__device__ __half g_wdh[(size_t)DM * DL], g_wdl[(size_t)DM * DL];
__device__ __half g_wukh[(size_t)DL * DM], g_wukl[(size_t)DL * DM];
__device__ __half g_wuvh[(size_t)DL * DM], g_wuvl[(size_t)DL * DM];
__device__ __half g_wqh[(size_t)DM * DM],  g_wql[(size_t)DM * DM];
__device__ __half g_woh[(size_t)DM * DM],  g_wol[(size_t)DM * DM];

// ---------------- helpers ------------------------------------------------------
__device__ __forceinline__ uint32_t smem_u32(const void* p) {
    uint32_t a;
    asm("{ .reg .u64 t; cvta.to.shared.u64 t, %1; cvt.u32.u64 %0, t; }" : "=r"(a) : "l"(p));
    return a;
}
__device__ __forceinline__ void cp_async16(uint32_t dst, const void* src) {
    asm volatile("cp.async.cg.shared.global [%0], [%1], 16;" :: "r"(dst), "l"(src) : "memory");
}
#define CP_COMMIT() asm volatile("cp.async.commit_group;" ::: "memory")
#define CP_WAIT1()  asm volatile("cp.async.wait_group 1;" ::: "memory")
#define CP_WAIT2()  asm volatile("cp.async.wait_group 2;" ::: "memory")
#define CP_WAIT3()  asm volatile("cp.async.wait_group 3;" ::: "memory")

__device__ __forceinline__ uint32_t pack_h2(float a, float b) {
    __half2 h = __float22half2_rn(make_float2(a, b));
    return *(uint32_t*)&h;
}
__device__ __forceinline__ void mma_f16(float* c, const uint32_t* a, const uint32_t* b) {
    asm volatile(
        "mma.sync.aligned.m16n8k16.row.col.f32.f16.f16.f32 "
        "{%0,%1,%2,%3}, {%4,%5,%6,%7}, {%8,%9}, {%0,%1,%2,%3};"
        : "+f"(c[0]), "+f"(c[1]), "+f"(c[2]), "+f"(c[3])
        : "r"(a[0]), "r"(a[1]), "r"(a[2]), "r"(a[3]), "r"(b[0]), "r"(b[1]));
}
__device__ __forceinline__ int inv_pair(int p) { return ((p & 3) << 1) | (p >> 2); }

// ---------------- prep: x->single fp16 + 5 weight transpose/splits -------------
__global__ void prep_kernel(const float* __restrict__ x,
                            const float* __restrict__ Wd, const float* __restrict__ Wuk,
                            const float* __restrict__ Wuv, const float* __restrict__ Wq,
                            const float* __restrict__ Wo)
{
    const int z = blockIdx.z;
    if (z == 0) {
        const int tid = threadIdx.y * 32 + threadIdx.x;
        long long base = ((long long)blockIdx.y * 64 + blockIdx.x) * 256 + tid;
        const long long tot = (long long)MTOT * DM / 2;
        for (long long i2 = base; i2 < tot; i2 += (long long)4096 * 256) {
            int d2 = (int)(i2 & (DM / 2 - 1));
            long long row = i2 >> 10;
            int d2p = (d2 & ~7) | inv_pair(d2 & 7);
            float2 v = ((const float2*)x)[i2];
            ((uint32_t*)g_xh)[row * (DM / 2) + d2p] = pack_h2(v.x, v.y);
        }
        return;
    }
    const float* in; __half *hi, *lo; int Cc, R;
    if      (z == 1) { in = Wd;  hi = g_wdh;  lo = g_wdl;  Cc = DL; R = DM; }
    else if (z == 2) { in = Wuk; hi = g_wukh; lo = g_wukl; Cc = DM; R = DL; }
    else if (z == 3) { in = Wuv; hi = g_wuvh; lo = g_wuvl; Cc = DM; R = DL; }
    else if (z == 4) { in = Wq;  hi = g_wqh;  lo = g_wql;  Cc = DM; R = DM; }
    else             { in = Wo;  hi = g_woh;  lo = g_wol;  Cc = DM; R = DM; }
    const int c0 = blockIdx.x * 32, r0 = blockIdx.y * 32;
    if (c0 >= Cc || r0 >= R) return;

    __shared__ float t[32][33];
#pragma unroll
    for (int i = threadIdx.y; i < 32; i += 8)
        t[i][threadIdx.x] = in[(long long)(r0 + i) * Cc + c0 + threadIdx.x];
    __syncthreads();
    const int e = r0 + threadIdx.x;
    const int p = e >> 1, bo = e & 1;
    const int pe = (((p & ~7) | inv_pair(p & 7)) << 1) | bo;
#pragma unroll
    for (int i = threadIdx.y; i < 32; i += 8) {
        float v = t[threadIdx.x][i];
        __half h = __float2half_rn(v);
        __half l = __float2half_rn(v - __half2float(h));
        hi[(long long)(c0 + i) * R + pe] = h;
        lo[(long long)(c0 + i) * R + pe] = l;
    }
}

// ---------------- 2-term fp16 GEMM: D = (A @ (Bh+Bl)^T + bias)*post ------------
// A single fp16 [M][K] (K pair-permuted), B hi/lo [N][K] (permuted).
#define BK 32
#define AROW 80
#define ARR (128 * AROW)
#define HSTAGE (3 * ARR)
// NOTE: must cover BOTH the 2-stage pipeline (61440 B) AND the Vt staging tile
// (128*132*4 = 67584 B). R15 crashed because this was 61440.
#define SMEM_HGEMM 67584

__global__ __launch_bounds__(256, 2)
void hgemm(const __half* __restrict__ Ah,
           const __half* __restrict__ Bh, const __half* __restrict__ Bl,
           float* __restrict__ Cf, __half* __restrict__ Ch,
           __half* __restrict__ VtH,
           const float* __restrict__ bias,
           int K, int lda, int ldb, int ldc, float post)
{
    extern __shared__ char sm[];
    const uint32_t smb = smem_u32(sm);
    const int tid = threadIdx.x, wid = tid >> 5, lane = tid & 31;
    const int qr = lane >> 2, qc = lane & 3;
    const int warpM = (wid & 1) * 64, warpN = (wid >> 1) * 32;
    const int m0 = blockIdx.y * 128, n0 = blockIdx.x * 128;

    const __half* A0 = Ah + (long long)m0 * lda;
    const __half* B0 = Bh + (long long)n0 * ldb;
    const __half* B1 = Bl + (long long)n0 * ldb;

    float acc[4][4][4];
#pragma unroll
    for (int mi = 0; mi < 4; mi++)
#pragma unroll
        for (int ni = 0; ni < 4; ni++)
#pragma unroll
            for (int t = 0; t < 4; t++) acc[mi][ni][t] = 0.0f;

    auto load_stage = [&](int t, int s) {
        const int k0 = t * BK;
        uint32_t base = smb + s * HSTAGE;
#pragma unroll
        for (int j = 0; j < 2; j++) {
            int g = tid + j * 256;
            int r = g >> 2, c = g & 3;
            uint32_t off = (uint32_t)(r * AROW + c * 16);
            cp_async16(base + off,           A0 + (long long)r * lda + k0 + c * 8);
            cp_async16(base + ARR + off,     B0 + (long long)r * ldb + k0 + c * 8);
            cp_async16(base + 2 * ARR + off, B1 + (long long)r * ldb + k0 + c * 8);
        }
    };

    const int nk = K / BK;
    load_stage(0, 0); CP_COMMIT();
    load_stage(1, 1); CP_COMMIT();

    for (int i = 0; i < nk; i++) {
        CP_WAIT1();
        __syncthreads();
        const char* s = sm + (i & 1) * HSTAGE;
#pragma unroll
        for (int kk = 0; kk < 2; kk++) {
            uint32_t aH[4][4], bH[4][2], bL[4][2];
#pragma unroll
            for (int mi = 0; mi < 4; mi++) {
                int row = warpM + mi * 16 + qr;
                uint2 v0 = *(const uint2*)(s + row * AROW + kk * 32 + qc * 8);
                uint2 v1 = *(const uint2*)(s + (row + 8) * AROW + kk * 32 + qc * 8);
                aH[mi][0] = v0.x; aH[mi][2] = v0.y; aH[mi][1] = v1.x; aH[mi][3] = v1.y;
            }
#pragma unroll
            for (int ni = 0; ni < 4; ni++) {
                int col = warpN + ni * 8 + qr;
                uint2 v = *(const uint2*)(s + ARR + col * AROW + kk * 32 + qc * 8);
                bH[ni][0] = v.x; bH[ni][1] = v.y;
                uint2 w = *(const uint2*)(s + 2 * ARR + col * AROW + kk * 32 + qc * 8);
                bL[ni][0] = w.x; bL[ni][1] = w.y;
            }
#pragma unroll
            for (int mi = 0; mi < 4; mi++)
#pragma unroll
                for (int ni = 0; ni < 4; ni++) {
                    mma_f16(acc[mi][ni], aH[mi], bL[ni]);
                    mma_f16(acc[mi][ni], aH[mi], bH[ni]);
                }
        }
        __syncthreads();
        if (i + 2 < nk) load_stage(i + 2, i & 1);
        CP_COMMIT();
    }

    if (VtH) {
        // V^T epilogue, coalesced permuted-group uint4 stores
        __syncthreads();
        float* tile = (float*)sm;   // [128 s][132 d] = 67584 B (fits SMEM_HGEMM)
#pragma unroll
        for (int mi = 0; mi < 4; mi++)
#pragma unroll
            for (int ni = 0; ni < 4; ni++) {
                int rl = warpM + mi * 16 + qr;
                int cl = warpN + ni * 8 + qc * 2;
                float2 bv = *(const float2*)(bias + n0 + cl);
                tile[rl * 132 + cl]       = acc[mi][ni][0] + bv.x;
                tile[rl * 132 + cl + 1]   = acc[mi][ni][1] + bv.y;
                tile[(rl + 8) * 132 + cl]     = acc[mi][ni][2] + bv.x;
                tile[(rl + 8) * 132 + cl + 1] = acc[mi][ni][3] + bv.y;
            }
        __syncthreads();
        const int h = n0 >> 7;
        const int bb = m0 >> 11;
        const int s0g = m0 & (SQ - 1);
        const int dl = tid & 127;
        const int sh = (tid >> 7) * 64;
        __half* orow = VtH + ((long long)(bb * NH + h) * DH + dl) * SQ + s0g + sh;
#pragma unroll
        for (int g = 0; g < 4; g++) {
            __half outh[16];
#pragma unroll
            for (int q = 0; q < 8; q++) {
                int sl = sh + g * 16 + 2 * q;
                int d = inv_pair(q) * 2;
                outh[d]     = __float2half_rn(tile[sl * 132 + dl]);
                outh[d + 1] = __float2half_rn(tile[(sl + 1) * 132 + dl]);
            }
            *(uint4*)(orow + g * 16)     = *(uint4*)&outh[0];
            *(uint4*)(orow + g * 16 + 8) = *(uint4*)&outh[8];
        }
        return;
    }

#pragma unroll
    for (int mi = 0; mi < 4; mi++) {
#pragma unroll
        for (int ni = 0; ni < 4; ni++) {
            int row = m0 + warpM + mi * 16 + qr;
            int colb = n0 + warpN + ni * 8;
            float2 bv = make_float2(0.f, 0.f);
            if (bias) bv = *(const float2*)(bias + colb + qc * 2);
            float2 v0 = make_float2((acc[mi][ni][0] + bv.x) * post, (acc[mi][ni][1] + bv.y) * post);
            float2 v1 = make_float2((acc[mi][ni][2] + bv.x) * post, (acc[mi][ni][3] + bv.y) * post);
            if (Cf) {
                *(float2*)(Cf + (long long)row * ldc + colb + qc * 2) = v0;
                *(float2*)(Cf + (long long)(row + 8) * ldc + colb + qc * 2) = v1;
            }
            if (Ch) {
                int p = (colb >> 1) + qc;
                int pp = (p & ~7) | inv_pair(p & 7);
                ((uint32_t*)Ch)[(long long)row * (ldc >> 1) + pp] = pack_h2(v0.x, v0.y);
                ((uint32_t*)Ch)[(long long)(row + 8) * (ldc >> 1) + pp] = pack_h2(v1.x, v1.y);
            }
        }
    }
}

// ---------------- fused flash attention: CHUNK=128, split K/V waits ------------
#define CHUNK 128
#define QROWB 272
#define KROWB 272
#define VROWB 272
#define SM_Q  0
#define KV0   (128 * QROWB)                // 34816
#define KVSTG (128 * KROWB + 128 * VROWB)  // 69632
#define FKH(s) (KV0 + (s) * KVSTG)
#define FV(s)  (KV0 + (s) * KVSTG + 128 * KROWB)
#define SMEM_FLASH (KV0 + 2 * KVSTG)       // 174080

__global__ __launch_bounds__(256, 1)
void flash_kernel(const __half* __restrict__ Qh,
                  const __half* __restrict__ Kh, const __half* __restrict__ Vh,
                  __half* __restrict__ Ch)
{
    extern __shared__ char smc[];
    const uint32_t smb = smem_u32(smc);
    const int tid = threadIdx.x, wid = tid >> 5, lane = tid & 31;
    const int qr = lane >> 2, qc = lane & 3;
    const int bh = blockIdx.y, b = bh >> 4, h = bh & 15;
    const int q0 = blockIdx.x * 128;

    const long long qbase = (long long)(b * SQ + q0);
    const __half* kh_g = Kh + (long long)(b * SQ) * DM + h * DH;
    const __half* vh_g = Vh + (long long)bh * DH * SQ;

    auto loadK = [&](int j, int s) {
        int s0 = j * CHUNK;
        for (int g = tid; g < 2048; g += 256) {
            int r = g >> 4, c = g & 15;
            cp_async16(smb + FKH(s) + r * KROWB + c * 16, kh_g + (long long)(s0 + r) * DM + c * 8);
        }
    };
    auto loadV = [&](int j, int s) {
        int s0 = j * CHUNK;
        for (int g = tid; g < 2048; g += 256) {
            int r = g >> 4, c = g & 15;
            cp_async16(smb + FV(s) + r * VROWB + c * 16, vh_g + (long long)r * SQ + s0 + c * 8);
        }
    };

    // prologue: group0 = Q + K0, group1 = V0
    {
        const __half* qh_g = Qh + qbase * DM + h * DH;
        for (int g = tid; g < 2048; g += 256) {
            int r = g >> 4, c = g & 15;
            cp_async16(smb + SM_Q + r * QROWB + c * 16, qh_g + (long long)r * DM + c * 8);
        }
    }
    loadK(0, 0); CP_COMMIT();
    loadV(0, 0); CP_COMMIT();

    float accO[16][4];
#pragma unroll
    for (int t = 0; t < 16; t++)
#pragma unroll
        for (int c = 0; c < 4; c++) accO[t][c] = 0.0f;
    float mr0 = -INFINITY, mr1 = -INFINITY, lr0 = 0.0f, lr1 = 0.0f;

    const char* qhp = smc + SM_Q + (wid * 16 + qr) * QROWB;

    const int NCH = SQ / CHUNK;   // 16
    for (int j = 0; j < NCH; j++) {
        if (j + 1 < NCH) {
            loadK(j + 1, (j + 1) & 1); CP_COMMIT();
            loadV(j + 1, (j + 1) & 1); CP_COMMIT();
        } else {
            CP_COMMIT(); CP_COMMIT();   // keep group ledger aligned
        }
        CP_WAIT3();                // K(j) (and Q) complete
        __syncthreads();
        const int st = j & 1;

        // ---- S = Q @ K^T (128 keys = 16 n8-tiles) ----
        float accS[16][4];
#pragma unroll
        for (int t = 0; t < 16; t++)
#pragma unroll
            for (int c = 0; c < 4; c++) accS[t][c] = 0.0f;
#pragma unroll
        for (int kk = 0; kk < 8; kk++) {
            uint32_t aH[4];
            {
                uint2 v0 = *(const uint2*)(qhp + kk * 32 + qc * 8);
                uint2 v1 = *(const uint2*)(qhp + 8 * QROWB + kk * 32 + qc * 8);
                aH[0] = v0.x; aH[2] = v0.y; aH[1] = v1.x; aH[3] = v1.y;
            }
#pragma unroll
            for (int t = 0; t < 16; t++) {
                uint2 bhv = *(const uint2*)(smc + FKH(st) + (8 * t + qr) * KROWB + kk * 32 + qc * 8);
                uint32_t bH[2] = {bhv.x, bhv.y};
                mma_f16(accS[t], aH, bH);
            }
        }

        // ---- online softmax max update ----
        float mx0 = -INFINITY, mx1 = -INFINITY;
#pragma unroll
        for (int t = 0; t < 16; t++) {
            mx0 = fmaxf(mx0, fmaxf(accS[t][0], accS[t][1]));
            mx1 = fmaxf(mx1, fmaxf(accS[t][2], accS[t][3]));
        }
        mx0 = fmaxf(mx0, __shfl_xor_sync(0xFFFFFFFFu, mx0, 1));
        mx0 = fmaxf(mx0, __shfl_xor_sync(0xFFFFFFFFu, mx0, 2));
        mx1 = fmaxf(mx1, __shfl_xor_sync(0xFFFFFFFFu, mx1, 1));
        mx1 = fmaxf(mx1, __shfl_xor_sync(0xFFFFFFFFu, mx1, 2));
        if (mx0 > mr0 || mx1 > mr1) {
            float mn0 = fmaxf(mr0, mx0), mn1 = fmaxf(mr1, mx1);
            float al0 = __expf(mr0 - mn0), al1 = __expf(mr1 - mn1);
            mr0 = mn0; mr1 = mn1;
            lr0 *= al0; lr1 *= al1;
#pragma unroll
            for (int t = 0; t < 16; t++) {
                accO[t][0] *= al0; accO[t][1] *= al0;
                accO[t][2] *= al1; accO[t][3] *= al1;
            }
        }

        CP_WAIT2();                // V(j) complete (landed during QK)
        __syncthreads();

        // ---- exp + PV in two t-halves (caps live registers) ----
#pragma unroll
        for (int h2 = 0; h2 < 2; h2++) {
            uint32_t ph[8][2];
#pragma unroll
            for (int u = 0; u < 8; u++) {
                int t = 8 * h2 + u;
                float p0 = __expf(accS[t][0] - mr0);
                float p1 = __expf(accS[t][1] - mr0);
                float p2 = __expf(accS[t][2] - mr1);
                float p3 = __expf(accS[t][3] - mr1);
                lr0 += p0 + p1;
                lr1 += p2 + p3;
                ph[u][0] = pack_h2(p0, p1);
                ph[u][1] = pack_h2(p2, p3);
            }
#pragma unroll
            for (int kk2 = 0; kk2 < 4; kk2++) {
                uint32_t aH[4] = {ph[2 * kk2][0], ph[2 * kk2][1],
                                  ph[2 * kk2 + 1][0], ph[2 * kk2 + 1][1]};
                int kko = (4 * h2 + kk2) * 32;
#pragma unroll
                for (int t = 0; t < 16; t++) {
                    uint2 vh2 = *(const uint2*)(smc + FV(st) + (8 * t + qr) * VROWB + kko + qc * 8);
                    uint32_t bV[2] = {vh2.x, vh2.y};
                    mma_f16(accO[t], aH, bV);
                }
            }
        }
        __syncthreads();           // buffers free for next loads
    }

    // ---- epilogue: normalize, store ctx single fp16 (permuted) ----
    lr0 += __shfl_xor_sync(0xFFFFFFFFu, lr0, 1);
    lr0 += __shfl_xor_sync(0xFFFFFFFFu, lr0, 2);
    lr1 += __shfl_xor_sync(0xFFFFFFFFu, lr1, 1);
    lr1 += __shfl_xor_sync(0xFFFFFFFFu, lr1, 2);
    const float i0 = 1.0f / lr0, i1 = 1.0f / lr1;
    const long long rowA = qbase + wid * 16 + qr;
#pragma unroll
    for (int t = 0; t < 16; t++) {
        int p = 64 * h + 4 * t + qc;
        int pp = (p & ~7) | inv_pair(p & 7);
        ((uint32_t*)Ch)[rowA * (DM / 2) + pp] = pack_h2(accO[t][0] * i0, accO[t][1] * i0);
        ((uint32_t*)Ch)[(rowA + 8) * (DM / 2) + pp] = pack_h2(accO[t][2] * i1, accO[t][3] * i1);
    }
}

// ---------------- launch -------------------------------------------------------
extern "C" void kernel_launch(void* const* d_in, const int* in_sizes, int n_in,
                              void* d_out, int out_size)
{
    const float* x      = (const float*)d_in[0];
    const float* W_down = (const float*)d_in[1];
    const float* b_down = (const float*)d_in[2];
    const float* W_uk   = (const float*)d_in[3];
    const float* b_uk   = (const float*)d_in[4];
    const float* W_uv   = (const float*)d_in[5];
    const float* b_uv   = (const float*)d_in[6];
    const float* W_q    = (const float*)d_in[7];
    const float* b_q    = (const float*)d_in[8];
    const float* W_o    = (const float*)d_in[9];
    const float* b_o    = (const float*)d_in[10];
    float* out = (float*)d_out;

    void *pa;
    cudaGetSymbolAddress(&pa, g_xh);    __half* xh = (__half*)pa;
    cudaGetSymbolAddress(&pa, g_lath);  __half* lath = (__half*)pa;
    cudaGetSymbolAddress(&pa, g_kh);    __half* kh = (__half*)pa;
    cudaGetSymbolAddress(&pa, g_qh);    __half* qh = (__half*)pa;
    cudaGetSymbolAddress(&pa, g_ctxh);  __half* ctxh = (__half*)pa;
    cudaGetSymbolAddress(&pa, g_vth);   __half* vth = (__half*)pa;
    __half *wdh, *wdl, *wukh, *wukl, *wuvh, *wuvl, *wqh, *wql, *woh, *wol;
    cudaGetSymbolAddress(&pa, g_wdh);  wdh  = (__half*)pa;
    cudaGetSymbolAddress(&pa, g_wdl);  wdl  = (__half*)pa;
    cudaGetSymbolAddress(&pa, g_wukh); wukh = (__half*)pa;
    cudaGetSymbolAddress(&pa, g_wukl); wukl = (__half*)pa;
    cudaGetSymbolAddress(&pa, g_wuvh); wuvh = (__half*)pa;
    cudaGetSymbolAddress(&pa, g_wuvl); wuvl = (__half*)pa;
    cudaGetSymbolAddress(&pa, g_wqh);  wqh  = (__half*)pa;
    cudaGetSymbolAddress(&pa, g_wql);  wql  = (__half*)pa;
    cudaGetSymbolAddress(&pa, g_woh);  woh  = (__half*)pa;
    cudaGetSymbolAddress(&pa, g_wol);  wol  = (__half*)pa;

    static bool attr_set = false;
    if (!attr_set) {
        cudaFuncSetAttribute(hgemm, cudaFuncAttributeMaxDynamicSharedMemorySize, SMEM_HGEMM);
        cudaFuncSetAttribute(flash_kernel, cudaFuncAttributeMaxDynamicSharedMemorySize, SMEM_FLASH);
        attr_set = true;
    }

    const float inv_sqrt_dh = 0.08838834764831845f;
    dim3 blk(256);

    // 0) prep
    prep_kernel<<<dim3(64, 64, 6), dim3(32, 8)>>>(x, W_down, W_uk, W_uv, W_q, W_o);

    // 1) q = (x @ W_q + b_q)/sqrt(DH) -> Q single fp16
    hgemm<<<dim3(DM/128, MTOT/128), blk, SMEM_HGEMM>>>(
        xh, wqh, wql, nullptr, qh, nullptr, b_q, DM, DM, DM, DM, inv_sqrt_dh);

    // 2) latents -> lat single fp16
    hgemm<<<dim3(DL/128, MTOT/128), blk, SMEM_HGEMM>>>(
        xh, wdh, wdl, nullptr, lath, nullptr, b_down, DM, DM, DM, DL, 1.0f);

    // 3) keys -> K single fp16
    hgemm<<<dim3(DM/128, MTOT/128), blk, SMEM_HGEMM>>>(
        lath, wukh, wukl, nullptr, kh, nullptr, b_uk, DL, DL, DL, DM, 1.0f);

    // 4) values -> V^T single fp16 (fused transpose)
    hgemm<<<dim3(DM/128, MTOT/128), blk, SMEM_HGEMM>>>(
        lath, wuvh, wuvl, nullptr, nullptr, vth, b_uv, DL, DL, DL, DM, 1.0f);

    // 5) flash attention -> ctx single fp16
    flash_kernel<<<dim3(SQ/128, BB*NH), blk, SMEM_FLASH>>>(qh, kh, vth, ctxh);

    // 6) out = ctx @ W_o + b_o
    hgemm<<<dim3(DM/128, MTOT/128), blk, SMEM_HGEMM>>>(
        ctxh, woh, wol, out, nullptr, nullptr, b_o, DM, DM, DM, DM, 1.0f);
}

// round 17
// speedup vs baseline: 2.3155x; 1.3315x over previous
#include <cuda_runtime.h>
#include <cuda_fp16.h>
#include <math.h>
#include <stdint.h>

#define SQ   2048
#define DM   2048
#define DH   128
#define NH   16
#define DL   512
#define BB   4
#define MTOT (BB*SQ)

// ---------------- scratch ------------------------------------------------------
__device__ __half g_xh[(size_t)MTOT * DM];
__device__ __half g_lath[(size_t)MTOT * DL];
__device__ __half g_kh[(size_t)MTOT * DM];
__device__ __half g_qh[(size_t)MTOT * DM];
__device__ __half g_ctxh[(size_t)MTOT * DM];
__device__ __half g_vth[(size_t)BB * NH * DH * SQ];
__device__ __half g_wdh[(size_t)DM * DL], g_wdl[(size_t)DM * DL];
__device__ __half g_wukh[(size_t)DL * DM], g_wukl[(size_t)DL * DM];
__device__ __half g_wuvh[(size_t)DL * DM], g_wuvl[(size_t)DL * DM];
__device__ __half g_wqh[(size_t)DM * DM],  g_wql[(size_t)DM * DM];
__device__ __half g_woh[(size_t)DM * DM],  g_wol[(size_t)DM * DM];

// ---------------- helpers ------------------------------------------------------
__device__ __forceinline__ uint32_t smem_u32(const void* p) {
    uint32_t a;
    asm("{ .reg .u64 t; cvta.to.shared.u64 t, %1; cvt.u32.u64 %0, t; }" : "=r"(a) : "l"(p));
    return a;
}
__device__ __forceinline__ void cp_async16(uint32_t dst, const void* src) {
    asm volatile("cp.async.cg.shared.global [%0], [%1], 16;" :: "r"(dst), "l"(src) : "memory");
}
#define CP_COMMIT() asm volatile("cp.async.commit_group;" ::: "memory")
#define CP_WAIT1()  asm volatile("cp.async.wait_group 1;" ::: "memory")
#define CP_WAIT2()  asm volatile("cp.async.wait_group 2;" ::: "memory")
#define CP_WAIT3()  asm volatile("cp.async.wait_group 3;" ::: "memory")

__device__ __forceinline__ uint32_t pack_h2(float a, float b) {
    __half2 h = __float22half2_rn(make_float2(a, b));
    return *(uint32_t*)&h;
}
__device__ __forceinline__ void mma_f16(float* c, const uint32_t* a, const uint32_t* b) {
    asm volatile(
        "mma.sync.aligned.m16n8k16.row.col.f32.f16.f16.f32 "
        "{%0,%1,%2,%3}, {%4,%5,%6,%7}, {%8,%9}, {%0,%1,%2,%3};"
        : "+f"(c[0]), "+f"(c[1]), "+f"(c[2]), "+f"(c[3])
        : "r"(a[0]), "r"(a[1]), "r"(a[2]), "r"(a[3]), "r"(b[0]), "r"(b[1]));
}
__device__ __forceinline__ int inv_pair(int p) { return ((p & 3) << 1) | (p >> 2); }

// ---------------- prep: x->single fp16 + 5 weight transpose/splits -------------
__global__ void prep_kernel(const float* __restrict__ x,
                            const float* __restrict__ Wd, const float* __restrict__ Wuk,
                            const float* __restrict__ Wuv, const float* __restrict__ Wq,
                            const float* __restrict__ Wo)
{
    const int z = blockIdx.z;
    if (z == 0) {
        const int tid = threadIdx.y * 32 + threadIdx.x;
        long long base = ((long long)blockIdx.y * 64 + blockIdx.x) * 256 + tid;
        const long long tot = (long long)MTOT * DM / 2;
        for (long long i2 = base; i2 < tot; i2 += (long long)4096 * 256) {
            int d2 = (int)(i2 & (DM / 2 - 1));
            long long row = i2 >> 10;
            int d2p = (d2 & ~7) | inv_pair(d2 & 7);
            float2 v = ((const float2*)x)[i2];
            ((uint32_t*)g_xh)[row * (DM / 2) + d2p] = pack_h2(v.x, v.y);
        }
        return;
    }
    const float* in; __half *hi, *lo; int Cc, R;
    if      (z == 1) { in = Wd;  hi = g_wdh;  lo = g_wdl;  Cc = DL; R = DM; }
    else if (z == 2) { in = Wuk; hi = g_wukh; lo = g_wukl; Cc = DM; R = DL; }
    else if (z == 3) { in = Wuv; hi = g_wuvh; lo = g_wuvl; Cc = DM; R = DL; }
    else if (z == 4) { in = Wq;  hi = g_wqh;  lo = g_wql;  Cc = DM; R = DM; }
    else             { in = Wo;  hi = g_woh;  lo = g_wol;  Cc = DM; R = DM; }
    const int c0 = blockIdx.x * 32, r0 = blockIdx.y * 32;
    if (c0 >= Cc || r0 >= R) return;

    __shared__ float t[32][33];
#pragma unroll
    for (int i = threadIdx.y; i < 32; i += 8)
        t[i][threadIdx.x] = in[(long long)(r0 + i) * Cc + c0 + threadIdx.x];
    __syncthreads();
    const int e = r0 + threadIdx.x;
    const int p = e >> 1, bo = e & 1;
    const int pe = (((p & ~7) | inv_pair(p & 7)) << 1) | bo;
#pragma unroll
    for (int i = threadIdx.y; i < 32; i += 8) {
        float v = t[threadIdx.x][i];
        __half h = __float2half_rn(v);
        __half l = __float2half_rn(v - __half2float(h));
        hi[(long long)(c0 + i) * R + pe] = h;
        lo[(long long)(c0 + i) * R + pe] = l;
    }
}

// ---------------- 2-term fp16 GEMM: D = (A @ (Bh+Bl)^T + bias)*post ------------
// A single fp16 [M][K] (K pair-permuted), B hi/lo [N][K] (permuted).
// AROW=96 B (24-word row shift): fragment LDS.64 loads are bank-conflict-free.
#define BK 32
#define AROW 96
#define ARR (128 * AROW)                  // 12288
#define HSTAGE (3 * ARR)                  // 36864
#define SMEM_HGEMM (2 * HSTAGE)           // 73728 (>= 67584 Vt staging tile)

__global__ __launch_bounds__(256, 2)
void hgemm(const __half* __restrict__ Ah,
           const __half* __restrict__ Bh, const __half* __restrict__ Bl,
           float* __restrict__ Cf, __half* __restrict__ Ch,
           __half* __restrict__ VtH,
           const float* __restrict__ bias,
           int K, int lda, int ldb, int ldc, float post)
{
    extern __shared__ char sm[];
    const uint32_t smb = smem_u32(sm);
    const int tid = threadIdx.x, wid = tid >> 5, lane = tid & 31;
    const int qr = lane >> 2, qc = lane & 3;
    const int warpM = (wid & 1) * 64, warpN = (wid >> 1) * 32;
    const int m0 = blockIdx.y * 128, n0 = blockIdx.x * 128;

    const __half* A0 = Ah + (long long)m0 * lda;
    const __half* B0 = Bh + (long long)n0 * ldb;
    const __half* B1 = Bl + (long long)n0 * ldb;

    float acc[4][4][4];
#pragma unroll
    for (int mi = 0; mi < 4; mi++)
#pragma unroll
        for (int ni = 0; ni < 4; ni++)
#pragma unroll
            for (int t = 0; t < 4; t++) acc[mi][ni][t] = 0.0f;

    auto load_stage = [&](int t, int s) {
        const int k0 = t * BK;
        uint32_t base = smb + s * HSTAGE;
#pragma unroll
        for (int j = 0; j < 2; j++) {
            int g = tid + j * 256;
            int r = g >> 2, c = g & 3;
            uint32_t off = (uint32_t)(r * AROW + c * 16);
            cp_async16(base + off,           A0 + (long long)r * lda + k0 + c * 8);
            cp_async16(base + ARR + off,     B0 + (long long)r * ldb + k0 + c * 8);
            cp_async16(base + 2 * ARR + off, B1 + (long long)r * ldb + k0 + c * 8);
        }
    };

    const int nk = K / BK;
    load_stage(0, 0); CP_COMMIT();
    load_stage(1, 1); CP_COMMIT();

    for (int i = 0; i < nk; i++) {
        CP_WAIT1();
        __syncthreads();
        const char* s = sm + (i & 1) * HSTAGE;
#pragma unroll
        for (int kk = 0; kk < 2; kk++) {
            uint32_t aH[4][4], bH[4][2], bL[4][2];
#pragma unroll
            for (int mi = 0; mi < 4; mi++) {
                int row = warpM + mi * 16 + qr;
                uint2 v0 = *(const uint2*)(s + row * AROW + kk * 32 + qc * 8);
                uint2 v1 = *(const uint2*)(s + (row + 8) * AROW + kk * 32 + qc * 8);
                aH[mi][0] = v0.x; aH[mi][2] = v0.y; aH[mi][1] = v1.x; aH[mi][3] = v1.y;
            }
#pragma unroll
            for (int ni = 0; ni < 4; ni++) {
                int col = warpN + ni * 8 + qr;
                uint2 v = *(const uint2*)(s + ARR + col * AROW + kk * 32 + qc * 8);
                bH[ni][0] = v.x; bH[ni][1] = v.y;
                uint2 w = *(const uint2*)(s + 2 * ARR + col * AROW + kk * 32 + qc * 8);
                bL[ni][0] = w.x; bL[ni][1] = w.y;
            }
#pragma unroll
            for (int mi = 0; mi < 4; mi++)
#pragma unroll
                for (int ni = 0; ni < 4; ni++) {
                    mma_f16(acc[mi][ni], aH[mi], bL[ni]);
                    mma_f16(acc[mi][ni], aH[mi], bH[ni]);
                }
        }
        __syncthreads();
        if (i + 2 < nk) load_stage(i + 2, i & 1);
        CP_COMMIT();
    }

    if (VtH) {
        // V^T epilogue, coalesced permuted-group uint4 stores
        __syncthreads();
        float* tile = (float*)sm;   // [128 s][132 d] = 67584 B (fits SMEM_HGEMM)
#pragma unroll
        for (int mi = 0; mi < 4; mi++)
#pragma unroll
            for (int ni = 0; ni < 4; ni++) {
                int rl = warpM + mi * 16 + qr;
                int cl = warpN + ni * 8 + qc * 2;
                float2 bv = *(const float2*)(bias + n0 + cl);
                tile[rl * 132 + cl]       = acc[mi][ni][0] + bv.x;
                tile[rl * 132 + cl + 1]   = acc[mi][ni][1] + bv.y;
                tile[(rl + 8) * 132 + cl]     = acc[mi][ni][2] + bv.x;
                tile[(rl + 8) * 132 + cl + 1] = acc[mi][ni][3] + bv.y;
            }
        __syncthreads();
        const int h = n0 >> 7;
        const int bb = m0 >> 11;
        const int s0g = m0 & (SQ - 1);
        const int dl = tid & 127;
        const int sh = (tid >> 7) * 64;
        __half* orow = VtH + ((long long)(bb * NH + h) * DH + dl) * SQ + s0g + sh;
#pragma unroll
        for (int g = 0; g < 4; g++) {
            __half outh[16];
#pragma unroll
            for (int q = 0; q < 8; q++) {
                int sl = sh + g * 16 + 2 * q;
                int d = inv_pair(q) * 2;
                outh[d]     = __float2half_rn(tile[sl * 132 + dl]);
                outh[d + 1] = __float2half_rn(tile[(sl + 1) * 132 + dl]);
            }
            *(uint4*)(orow + g * 16)     = *(uint4*)&outh[0];
            *(uint4*)(orow + g * 16 + 8) = *(uint4*)&outh[8];
        }
        return;
    }

#pragma unroll
    for (int mi = 0; mi < 4; mi++) {
#pragma unroll
        for (int ni = 0; ni < 4; ni++) {
            int row = m0 + warpM + mi * 16 + qr;
            int colb = n0 + warpN + ni * 8;
            float2 bv = make_float2(0.f, 0.f);
            if (bias) bv = *(const float2*)(bias + colb + qc * 2);
            float2 v0 = make_float2((acc[mi][ni][0] + bv.x) * post, (acc[mi][ni][1] + bv.y) * post);
            float2 v1 = make_float2((acc[mi][ni][2] + bv.x) * post, (acc[mi][ni][3] + bv.y) * post);
            if (Cf) {
                *(float2*)(Cf + (long long)row * ldc + colb + qc * 2) = v0;
                *(float2*)(Cf + (long long)(row + 8) * ldc + colb + qc * 2) = v1;
            }
            if (Ch) {
                int p = (colb >> 1) + qc;
                int pp = (p & ~7) | inv_pair(p & 7);
                ((uint32_t*)Ch)[(long long)row * (ldc >> 1) + pp] = pack_h2(v0.x, v0.y);
                ((uint32_t*)Ch)[(long long)(row + 8) * (ldc >> 1) + pp] = pack_h2(v1.x, v1.y);
            }
        }
    }
}

// ---------------- fused flash attention: CHUNK=128, conflict-free 288B pitch ---
#define CHUNK 128
#define QROWB 288
#define KROWB 288
#define VROWB 288
#define SM_Q  0
#define KV0   (128 * QROWB)                // 36864
#define KVSTG (128 * KROWB + 128 * VROWB)  // 73728
#define FKH(s) (KV0 + (s) * KVSTG)
#define FV(s)  (KV0 + (s) * KVSTG + 128 * KROWB)
#define SMEM_FLASH (KV0 + 2 * KVSTG)       // 184320

__global__ __launch_bounds__(256, 1)
void flash_kernel(const __half* __restrict__ Qh,
                  const __half* __restrict__ Kh, const __half* __restrict__ Vh,
                  __half* __restrict__ Ch)
{
    extern __shared__ char smc[];
    const uint32_t smb = smem_u32(smc);
    const int tid = threadIdx.x, wid = tid >> 5, lane = tid & 31;
    const int qr = lane >> 2, qc = lane & 3;
    const int bh = blockIdx.y, b = bh >> 4, h = bh & 15;
    const int q0 = blockIdx.x * 128;

    const long long qbase = (long long)(b * SQ + q0);
    const __half* kh_g = Kh + (long long)(b * SQ) * DM + h * DH;
    const __half* vh_g = Vh + (long long)bh * DH * SQ;

    auto loadK = [&](int j, int s) {
        int s0 = j * CHUNK;
        for (int g = tid; g < 2048; g += 256) {
            int r = g >> 4, c = g & 15;
            cp_async16(smb + FKH(s) + r * KROWB + c * 16, kh_g + (long long)(s0 + r) * DM + c * 8);
        }
    };
    auto loadV = [&](int j, int s) {
        int s0 = j * CHUNK;
        for (int g = tid; g < 2048; g += 256) {
            int r = g >> 4, c = g & 15;
            cp_async16(smb + FV(s) + r * VROWB + c * 16, vh_g + (long long)r * SQ + s0 + c * 8);
        }
    };

    // prologue: group0 = Q + K0, group1 = V0
    {
        const __half* qh_g = Qh + qbase * DM + h * DH;
        for (int g = tid; g < 2048; g += 256) {
            int r = g >> 4, c = g & 15;
            cp_async16(smb + SM_Q + r * QROWB + c * 16, qh_g + (long long)r * DM + c * 8);
        }
    }
    loadK(0, 0); CP_COMMIT();
    loadV(0, 0); CP_COMMIT();

    float accO[16][4];
#pragma unroll
    for (int t = 0; t < 16; t++)
#pragma unroll
        for (int c = 0; c < 4; c++) accO[t][c] = 0.0f;
    float mr0 = -INFINITY, mr1 = -INFINITY, lr0 = 0.0f, lr1 = 0.0f;

    const char* qhp = smc + SM_Q + (wid * 16 + qr) * QROWB;

    const int NCH = SQ / CHUNK;   // 16
    for (int j = 0; j < NCH; j++) {
        if (j + 1 < NCH) {
            loadK(j + 1, (j + 1) & 1); CP_COMMIT();
            loadV(j + 1, (j + 1) & 1); CP_COMMIT();
        } else {
            CP_COMMIT(); CP_COMMIT();   // keep group ledger aligned
        }
        CP_WAIT3();                // K(j) (and Q) complete
        __syncthreads();
        const int st = j & 1;

        // ---- S = Q @ K^T (128 keys = 16 n8-tiles) ----
        float accS[16][4];
#pragma unroll
        for (int t = 0; t < 16; t++)
#pragma unroll
            for (int c = 0; c < 4; c++) accS[t][c] = 0.0f;
#pragma unroll
        for (int kk = 0; kk < 8; kk++) {
            uint32_t aH[4];
            {
                uint2 v0 = *(const uint2*)(qhp + kk * 32 + qc * 8);
                uint2 v1 = *(const uint2*)(qhp + 8 * QROWB + kk * 32 + qc * 8);
                aH[0] = v0.x; aH[2] = v0.y; aH[1] = v1.x; aH[3] = v1.y;
            }
#pragma unroll
            for (int t = 0; t < 16; t++) {
                uint2 bhv = *(const uint2*)(smc + FKH(st) + (8 * t + qr) * KROWB + kk * 32 + qc * 8);
                uint32_t bH[2] = {bhv.x, bhv.y};
                mma_f16(accS[t], aH, bH);
            }
        }

        // ---- online softmax max update ----
        float mx0 = -INFINITY, mx1 = -INFINITY;
#pragma unroll
        for (int t = 0; t < 16; t++) {
            mx0 = fmaxf(mx0, fmaxf(accS[t][0], accS[t][1]));
            mx1 = fmaxf(mx1, fmaxf(accS[t][2], accS[t][3]));
        }
        mx0 = fmaxf(mx0, __shfl_xor_sync(0xFFFFFFFFu, mx0, 1));
        mx0 = fmaxf(mx0, __shfl_xor_sync(0xFFFFFFFFu, mx0, 2));
        mx1 = fmaxf(mx1, __shfl_xor_sync(0xFFFFFFFFu, mx1, 1));
        mx1 = fmaxf(mx1, __shfl_xor_sync(0xFFFFFFFFu, mx1, 2));
        if (mx0 > mr0 || mx1 > mr1) {
            float mn0 = fmaxf(mr0, mx0), mn1 = fmaxf(mr1, mx1);
            float al0 = __expf(mr0 - mn0), al1 = __expf(mr1 - mn1);
            mr0 = mn0; mr1 = mn1;
            lr0 *= al0; lr1 *= al1;
#pragma unroll
            for (int t = 0; t < 16; t++) {
                accO[t][0] *= al0; accO[t][1] *= al0;
                accO[t][2] *= al1; accO[t][3] *= al1;
            }
        }

        CP_WAIT2();                // V(j) complete (landed during QK)
        __syncthreads();

        // ---- exp + PV in two t-halves (caps live registers) ----
#pragma unroll
        for (int h2 = 0; h2 < 2; h2++) {
            uint32_t ph[8][2];
#pragma unroll
            for (int u = 0; u < 8; u++) {
                int t = 8 * h2 + u;
                float p0 = __expf(accS[t][0] - mr0);
                float p1 = __expf(accS[t][1] - mr0);
                float p2 = __expf(accS[t][2] - mr1);
                float p3 = __expf(accS[t][3] - mr1);
                lr0 += p0 + p1;
                lr1 += p2 + p3;
                ph[u][0] = pack_h2(p0, p1);
                ph[u][1] = pack_h2(p2, p3);
            }
#pragma unroll
            for (int kk2 = 0; kk2 < 4; kk2++) {
                uint32_t aH[4] = {ph[2 * kk2][0], ph[2 * kk2][1],
                                  ph[2 * kk2 + 1][0], ph[2 * kk2 + 1][1]};
                int kko = (4 * h2 + kk2) * 32;
#pragma unroll
                for (int t = 0; t < 16; t++) {
                    uint2 vh2 = *(const uint2*)(smc + FV(st) + (8 * t + qr) * VROWB + kko + qc * 8);
                    uint32_t bV[2] = {vh2.x, vh2.y};
                    mma_f16(accO[t], aH, bV);
                }
            }
        }
        __syncthreads();           // buffers free for next loads
    }

    // ---- epilogue: normalize, store ctx single fp16 (permuted) ----
    lr0 += __shfl_xor_sync(0xFFFFFFFFu, lr0, 1);
    lr0 += __shfl_xor_sync(0xFFFFFFFFu, lr0, 2);
    lr1 += __shfl_xor_sync(0xFFFFFFFFu, lr1, 1);
    lr1 += __shfl_xor_sync(0xFFFFFFFFu, lr1, 2);
    const float i0 = 1.0f / lr0, i1 = 1.0f / lr1;
    const long long rowA = qbase + wid * 16 + qr;
#pragma unroll
    for (int t = 0; t < 16; t++) {
        int p = 64 * h + 4 * t + qc;
        int pp = (p & ~7) | inv_pair(p & 7);
        ((uint32_t*)Ch)[rowA * (DM / 2) + pp] = pack_h2(accO[t][0] * i0, accO[t][1] * i0);
        ((uint32_t*)Ch)[(rowA + 8) * (DM / 2) + pp] = pack_h2(accO[t][2] * i1, accO[t][3] * i1);
    }
}

// ---------------- launch -------------------------------------------------------
extern "C" void kernel_launch(void* const* d_in, const int* in_sizes, int n_in,
                              void* d_out, int out_size)
{
    const float* x      = (const float*)d_in[0];
    const float* W_down = (const float*)d_in[1];
    const float* b_down = (const float*)d_in[2];
    const float* W_uk   = (const float*)d_in[3];
    const float* b_uk   = (const float*)d_in[4];
    const float* W_uv   = (const float*)d_in[5];
    const float* b_uv   = (const float*)d_in[6];
    const float* W_q    = (const float*)d_in[7];
    const float* b_q    = (const float*)d_in[8];
    const float* W_o    = (const float*)d_in[9];
    const float* b_o    = (const float*)d_in[10];
    float* out = (float*)d_out;

    void *pa;
    cudaGetSymbolAddress(&pa, g_xh);    __half* xh = (__half*)pa;
    cudaGetSymbolAddress(&pa, g_lath);  __half* lath = (__half*)pa;
    cudaGetSymbolAddress(&pa, g_kh);    __half* kh = (__half*)pa;
    cudaGetSymbolAddress(&pa, g_qh);    __half* qh = (__half*)pa;
    cudaGetSymbolAddress(&pa, g_ctxh);  __half* ctxh = (__half*)pa;
    cudaGetSymbolAddress(&pa, g_vth);   __half* vth = (__half*)pa;
    __half *wdh, *wdl, *wukh, *wukl, *wuvh, *wuvl, *wqh, *wql, *woh, *wol;
    cudaGetSymbolAddress(&pa, g_wdh);  wdh  = (__half*)pa;
    cudaGetSymbolAddress(&pa, g_wdl);  wdl  = (__half*)pa;
    cudaGetSymbolAddress(&pa, g_wukh); wukh = (__half*)pa;
    cudaGetSymbolAddress(&pa, g_wukl); wukl = (__half*)pa;
    cudaGetSymbolAddress(&pa, g_wuvh); wuvh = (__half*)pa;
    cudaGetSymbolAddress(&pa, g_wuvl); wuvl = (__half*)pa;
    cudaGetSymbolAddress(&pa, g_wqh);  wqh  = (__half*)pa;
    cudaGetSymbolAddress(&pa, g_wql);  wql  = (__half*)pa;
    cudaGetSymbolAddress(&pa, g_woh);  woh  = (__half*)pa;
    cudaGetSymbolAddress(&pa, g_wol);  wol  = (__half*)pa;

    static bool attr_set = false;
    if (!attr_set) {
        cudaFuncSetAttribute(hgemm, cudaFuncAttributeMaxDynamicSharedMemorySize, SMEM_HGEMM);
        cudaFuncSetAttribute(flash_kernel, cudaFuncAttributeMaxDynamicSharedMemorySize, SMEM_FLASH);
        attr_set = true;
    }

    const float inv_sqrt_dh = 0.08838834764831845f;
    dim3 blk(256);

    // 0) prep
    prep_kernel<<<dim3(64, 64, 6), dim3(32, 8)>>>(x, W_down, W_uk, W_uv, W_q, W_o);

    // 1) q = (x @ W_q + b_q)/sqrt(DH) -> Q single fp16
    hgemm<<<dim3(DM/128, MTOT/128), blk, SMEM_HGEMM>>>(
        xh, wqh, wql, nullptr, qh, nullptr, b_q, DM, DM, DM, DM, inv_sqrt_dh);

    // 2) latents -> lat single fp16
    hgemm<<<dim3(DL/128, MTOT/128), blk, SMEM_HGEMM>>>(
        xh, wdh, wdl, nullptr, lath, nullptr, b_down, DM, DM, DM, DL, 1.0f);

    // 3) keys -> K single fp16
    hgemm<<<dim3(DM/128, MTOT/128), blk, SMEM_HGEMM>>>(
        lath, wukh, wukl, nullptr, kh, nullptr, b_uk, DL, DL, DL, DM, 1.0f);

    // 4) values -> V^T single fp16 (fused transpose)
    hgemm<<<dim3(DM/128, MTOT/128), blk, SMEM_HGEMM>>>(
        lath, wuvh, wuvl, nullptr, nullptr, vth, b_uv, DL, DL, DL, DM, 1.0f);

    // 5) flash attention -> ctx single fp16
    flash_kernel<<<dim3(SQ/128, BB*NH), blk, SMEM_FLASH>>>(qh, kh, vth, ctxh);

    // 6) out = ctx @ W_o + b_o
    hgemm<<<dim3(DM/128, MTOT/128), blk, SMEM_HGEMM>>>(
        ctxh, woh, wol, out, nullptr, nullptr, b_o, DM, DM, DM, DM, 1.0f);
}